// round 8
// baseline (speedup 1.0000x reference)
#include <cuda_runtime.h>
#include <cuda_bf16.h>
#include <cstdint>

// PatchAttentionLayer on GB300 (sm_103 baseline PTX path).
// BN folded into affine maps; attention via associativity (no NxN map).
// All big GEMMs on mma.sync bf16 hi/lo. R6: glue chain t1/m/p replaced by
// R = Ak^T Aq (batch-indep) + tensor-core T2 = G*R and P = Av*T2 + rank-1.

#define CCH 256
#define BATCH 8
#define HWN 4096
#define EPS_BN 1e-5f
#define INV_NPOS (1.0f / 32768.0f)
#define SCALE 0.125f

// ================= device scratch =================
__device__ __nv_bfloat16 g_xh[BATCH][CCH][HWN];
__device__ __nv_bfloat16 g_xl[BATCH][CCH][HWN];
__device__ float g_S1p[4][BATCH][CCH][CCH];
__device__ float g_S2p[4][BATCH][CCH][CCH];
__device__ float g_s[BATCH][CCH];
__device__ float g_mean[CCH];
__device__ float g_Cov[CCH][CCH];
__device__ float g_A[3][CCH][CCH];
__device__ float g_cvec[3][CCH];
__device__ float g_G[BATCH][CCH][CCH];
__device__ __nv_bfloat16 g_Gh[BATCH][CCH][CCH], g_Gl[BATCH][CCH][CCH];
__device__ float g_R[CCH][CCH];
__device__ __nv_bfloat16 g_Rh[CCH][CCH], g_Rl[CCH][CCH];
__device__ __nv_bfloat16 g_Avh[CCH][CCH], g_Avl[CCH][CCH];
__device__ __nv_bfloat16 g_T2h[BATCH][CCH][CCH], g_T2l[BATCH][CCH][CCH];
__device__ float g_r1[CCH], g_a1[CCH], g_cc1;
__device__ float g_d[BATCH][CCH];
__device__ __nv_bfloat16 g_Ph[BATCH][CCH][CCH];
__device__ __nv_bfloat16 g_Pl[BATCH][CCH][CCH];

// ================= mma helpers =================
__device__ __forceinline__ uint32_t smem_u32(const void* p) {
    uint32_t a;
    asm("{ .reg .u64 t; cvta.to.shared.u64 t, %1; cvt.u32.u64 %0, t; }" : "=r"(a) : "l"(p));
    return a;
}
__device__ __forceinline__ void ldsm4(uint32_t* r, uint32_t a) {
    asm volatile("ldmatrix.sync.aligned.m8n8.x4.shared.b16 {%0,%1,%2,%3}, [%4];"
                 : "=r"(r[0]), "=r"(r[1]), "=r"(r[2]), "=r"(r[3]) : "r"(a));
}
__device__ __forceinline__ void ldsm4t(uint32_t* r, uint32_t a) {
    asm volatile("ldmatrix.sync.aligned.m8n8.x4.trans.shared.b16 {%0,%1,%2,%3}, [%4];"
                 : "=r"(r[0]), "=r"(r[1]), "=r"(r[2]), "=r"(r[3]) : "r"(a));
}
__device__ __forceinline__ void mma_bf16(float* c, const uint32_t* a, const uint32_t* b) {
    asm volatile(
        "mma.sync.aligned.m16n8k16.row.col.f32.bf16.bf16.f32 "
        "{%0,%1,%2,%3},{%4,%5,%6,%7},{%8,%9},{%0,%1,%2,%3};"
        : "+f"(c[0]), "+f"(c[1]), "+f"(c[2]), "+f"(c[3])
        : "r"(a[0]), "r"(a[1]), "r"(a[2]), "r"(a[3]), "r"(b[0]), "r"(b[1]));
}
#define CPA16(dst, src) asm volatile("cp.async.cg.shared.global [%0], [%1], 16;" :: "r"(dst), "l"(src))
#define CPA_COMMIT()    asm volatile("cp.async.commit_group;")
#define CPA_WAIT1()     asm volatile("cp.async.wait_group 1;")
#define CPA_WAIT0()     asm volatile("cp.async.wait_group 0;")

__device__ __forceinline__ void split_store(__nv_bfloat16* ph, __nv_bfloat16* pl, float v) {
    __nv_bfloat16 h = __float2bfloat16(v);
    *ph = h;
    *pl = __float2bfloat16(v - __bfloat162float(h));
}

// ================= prep =================
__global__ __launch_bounds__(256) void prep_kernel(const float* __restrict__ x) {
    int c = blockIdx.x, b = blockIdx.y;
    const float4* src = (const float4*)(x + ((long)(b * CCH + c)) * HWN);
    __nv_bfloat162* dh = (__nv_bfloat162*)&g_xh[b][c][0];
    __nv_bfloat162* dl = (__nv_bfloat162*)&g_xl[b][c][0];
    float s = 0.f;
    for (int i = threadIdx.x; i < 1024; i += 256) {
        float4 v = src[i];
        s += (v.x + v.y) + (v.z + v.w);
        __nv_bfloat16 h0 = __float2bfloat16(v.x), h1 = __float2bfloat16(v.y);
        __nv_bfloat16 h2 = __float2bfloat16(v.z), h3 = __float2bfloat16(v.w);
        __nv_bfloat162 hh0; hh0.x = h0; hh0.y = h1;
        __nv_bfloat162 hh1; hh1.x = h2; hh1.y = h3;
        __nv_bfloat162 ll0, ll1;
        ll0.x = __float2bfloat16(v.x - __bfloat162float(h0));
        ll0.y = __float2bfloat16(v.y - __bfloat162float(h1));
        ll1.x = __float2bfloat16(v.z - __bfloat162float(h2));
        ll1.y = __float2bfloat16(v.w - __bfloat162float(h3));
        dh[2 * i] = hh0; dh[2 * i + 1] = hh1;
        dl[2 * i] = ll0; dl[2 * i + 1] = ll1;
    }
    __shared__ float sh[256];
    sh[threadIdx.x] = s;
    __syncthreads();
    for (int off = 128; off > 0; off >>= 1) {
        if (threadIdx.x < off) sh[threadIdx.x] += sh[threadIdx.x + off];
        __syncthreads();
    }
    if (threadIdx.x == 0) g_s[b][c] = sh[0];
}

// ================= gram: S1 = H H^T and S2 = H L^T fused =================
#define GR_TILE 10240
#define GR_BUF  (3 * GR_TILE)
#define GR_SMEM (2 * GR_BUF)

__global__ __launch_bounds__(512) void gram_mma_kernel() {
    extern __shared__ char smem[];
    uint32_t sb = smem_u32(smem);
    int t = threadIdx.x, lane = t & 31, wid = t >> 5;
    int split = blockIdx.x, b = blockIdx.z;
    int mt = blockIdx.y >> 1, nt = blockIdx.y & 1;
    const __nv_bfloat16* Ag  = &g_xh[b][mt * 128][0];
    const __nv_bfloat16* BgH = &g_xh[b][nt * 128][0];
    const __nv_bfloat16* BgL = &g_xl[b][nt * 128][0];
    int k0 = split * 1024;
    int grp = wid >> 3, w8 = wid & 7;
    int wm = (w8 >> 2) * 64, wn = (w8 & 3) * 32;

    float acc[4][4][4] = {};

    auto stage = [&](int buf, int kk) {
        uint32_t base = sb + buf * GR_BUF;
        int r = t >> 2, c = t & 3;
        long go = (long)r * HWN + kk + c * 8;
        uint32_t so = r * 80 + c * 16;
        CPA16(base + so,               (const char*)(Ag + go));
        CPA16(base + GR_TILE + so,     (const char*)(BgH + go));
        CPA16(base + 2 * GR_TILE + so, (const char*)(BgL + go));
    };

    stage(0, k0);
    CPA_COMMIT();
    const int S = 32;
    for (int s = 0; s < S; s++) {
        if (s + 1 < S) { stage((s + 1) & 1, k0 + (s + 1) * 32); CPA_COMMIT(); CPA_WAIT1(); }
        else CPA_WAIT0();
        __syncthreads();
        uint32_t aBase = sb + (s & 1) * GR_BUF;
        uint32_t bBase = aBase + GR_TILE + grp * GR_TILE;
#pragma unroll
        for (int ks = 0; ks < 32; ks += 16) {
            uint32_t af[4][4], bf[4][2];
#pragma unroll
            for (int i = 0; i < 4; i++)
                ldsm4(af[i], aBase + (wm + i * 16 + (lane & 15)) * 80 + ks * 2 + (lane >> 4) * 16);
#pragma unroll
            for (int j = 0; j < 2; j++) {
                uint32_t r[4];
                ldsm4(r, bBase + (wn + j * 16 + (lane & 15)) * 80 + ks * 2 + (lane >> 4) * 16);
                bf[2 * j][0] = r[0]; bf[2 * j][1] = r[2];
                bf[2 * j + 1][0] = r[1]; bf[2 * j + 1][1] = r[3];
            }
#pragma unroll
            for (int i = 0; i < 4; i++)
#pragma unroll
                for (int j = 0; j < 4; j++) mma_bf16(acc[i][j], af[i], bf[j]);
        }
        __syncthreads();
    }

    float* dst = grp ? &g_S2p[split][b][0][0] : &g_S1p[split][b][0][0];
#pragma unroll
    for (int i = 0; i < 4; i++) {
        int m = mt * 128 + wm + i * 16 + (lane >> 2);
#pragma unroll
        for (int j = 0; j < 4; j++) {
            int n = nt * 128 + wn + j * 8 + (lane & 3) * 2;
            *(float2*)(dst + (long)m * CCH + n) = make_float2(acc[i][j][0], acc[i][j][1]);
            *(float2*)(dst + (long)(m + 8) * CCH + n) = make_float2(acc[i][j][2], acc[i][j][3]);
        }
    }
}

// G[b] = sum_s (S1 + S2) + (sum_s S2)^T  (+ bf16 hi/lo split)
__global__ __launch_bounds__(256) void reduceG_kernel() {
    __shared__ float tt[32][33];
    int jt = blockIdx.x * 32, it = blockIdx.y * 32, b = blockIdx.z;
    int lx = threadIdx.x & 31, ly = threadIdx.x >> 5;
    for (int r = ly; r < 32; r += 8) {
        float s = 0.f;
#pragma unroll
        for (int sp = 0; sp < 4; sp++) s += g_S2p[sp][b][jt + r][it + lx];
        tt[r][lx] = s;
    }
    __syncthreads();
    for (int r = ly; r < 32; r += 8) {
        float s = tt[lx][r];
#pragma unroll
        for (int sp = 0; sp < 4; sp++)
            s += g_S1p[sp][b][it + r][jt + lx] + g_S2p[sp][b][it + r][jt + lx];
        g_G[b][it + r][jt + lx] = s;
        split_store(&g_Gh[b][it + r][jt + lx], &g_Gl[b][it + r][jt + lx], s);
    }
}

// ================= cov (+mean fused) =================
__global__ void cov_kernel() {
    int c = blockIdx.x, t = threadIdx.x;
    float mt_ = 0.f;
#pragma unroll
    for (int b = 0; b < BATCH; b++) mt_ += g_s[b][t];
    mt_ *= INV_NPOS;
    __shared__ float mc_sh;
    if (t == c) mc_sh = mt_;
    __syncthreads();
    float s = 0.f;
#pragma unroll
    for (int b = 0; b < BATCH; b++) s += g_G[b][c][t];
    g_Cov[c][t] = s * INV_NPOS - mc_sh * mt_;
    if (c == 0) g_mean[t] = mt_;
}

// ================= BN fold (+ Av split for P kernel) =================
__global__ void proj_kernel(
    const float* __restrict__ Wq, const float* __restrict__ bq, const float* __restrict__ gq, const float* __restrict__ beq,
    const float* __restrict__ Wk, const float* __restrict__ bk, const float* __restrict__ gk, const float* __restrict__ bek,
    const float* __restrict__ Wv, const float* __restrict__ bv, const float* __restrict__ gv, const float* __restrict__ bev) {
    int o = blockIdx.x, tp = blockIdx.y;
    const float *W, *bb, *gg, *be;
    if (tp == 0) { W = Wq; bb = bq; gg = gq; be = beq; }
    else if (tp == 1) { W = Wk; bb = bk; gg = gk; be = bek; }
    else { W = Wv; bb = bv; gg = gv; be = bev; }
    __shared__ float ws[CCH];
    int t = threadIdx.x;
    ws[t] = W[o * CCH + t];
    __syncthreads();
    float col = 0.f;
    for (int c = 0; c < CCH; c++) col += ws[c] * g_Cov[c][t];
    __shared__ float s1[256], s2[256];
    s1[t] = col * ws[t]; s2[t] = ws[t] * g_mean[t];
    __syncthreads();
    for (int off = 128; off > 0; off >>= 1) {
        if (t < off) { s1[t] += s1[t + off]; s2[t] += s2[t + off]; }
        __syncthreads();
    }
    __shared__ float a_sh, c_sh;
    if (t == 0) {
        float var = s1[0];
        float mu = s2[0] + bb[o];
        float a = gg[o] * rsqrtf(var + EPS_BN);
        a_sh = a;
        c_sh = (bb[o] - mu) * a + be[o];
    }
    __syncthreads();
    float av = a_sh * ws[t];
    g_A[tp][o][t] = av;
    if (tp == 2) split_store(&g_Avh[o][t], &g_Avl[o][t], av);
    if (t == 0) g_cvec[tp][o] = c_sh;
}

// ================= R = Ak^T Aq (fp32, 32x32 tiles) + r1/a1/cc1 =================
__global__ __launch_bounds__(256) void rk_kernel() {
    __shared__ float a[16][33], bsh[16][33];
    int i0 = blockIdx.x * 32, j0 = blockIdx.y * 32;
    int t = threadIdx.x, tx = t & 15, ty = t >> 4;
    float acc[2][2] = {};
    for (int o0 = 0; o0 < CCH; o0 += 16) {
        for (int idx = t; idx < 512; idx += 256) {
            int kk = idx >> 5, c = idx & 31;
            a[kk][c]   = g_A[1][o0 + kk][i0 + c];
            bsh[kk][c] = g_A[0][o0 + kk][j0 + c];
        }
        __syncthreads();
#pragma unroll
        for (int kk = 0; kk < 16; kk++) {
            float av0 = a[kk][ty * 2], av1 = a[kk][ty * 2 + 1];
            float bv0 = bsh[kk][tx * 2], bv1 = bsh[kk][tx * 2 + 1];
            acc[0][0] += av0 * bv0; acc[0][1] += av0 * bv1;
            acc[1][0] += av1 * bv0; acc[1][1] += av1 * bv1;
        }
        __syncthreads();
    }
#pragma unroll
    for (int i = 0; i < 2; i++)
#pragma unroll
        for (int j = 0; j < 2; j++) {
            int ri = i0 + ty * 2 + i, cj = j0 + tx * 2 + j;
            g_R[ri][cj] = acc[i][j];
            split_store(&g_Rh[ri][cj], &g_Rl[ri][cj], acc[i][j]);
        }
    if (blockIdx.x == 0 && blockIdx.y == 0) {
        __shared__ float cks[CCH], cqs[CCH], red[256];
        cks[t] = g_cvec[1][t]; cqs[t] = g_cvec[0][t];
        __syncthreads();
        float rr = 0.f, aa = 0.f;
        for (int o = 0; o < CCH; o++) {
            rr += g_A[1][o][t] * cqs[o];
            aa += g_A[0][o][t] * cks[o];
        }
        g_r1[t] = rr; g_a1[t] = aa;
        red[t] = cks[t] * cqs[t];
        __syncthreads();
        for (int off = 128; off > 0; off >>= 1) {
            if (t < off) red[t] += red[t + off];
            __syncthreads();
        }
        if (t == 0) g_cc1 = red[0];
    }
}

// ================= vec: t2v = G r1; d = SCALE(Av t2v + u cc1 + cv(s.r1 + 4096 cc1)) ===
__global__ __launch_bounds__(256) void vec_kernel() {
    int b = blockIdx.x, t = threadIdx.x, lane = t & 31, wid = t >> 5;
    __shared__ float r1s[CCH], ss[CCH], t2vs[CCH], red[256];
    r1s[t] = g_r1[t]; ss[t] = g_s[b][t];
    __syncthreads();
    red[t] = ss[t] * r1s[t];
    __syncthreads();
    for (int off = 128; off > 0; off >>= 1) {
        if (t < off) red[t] += red[t + off];
        __syncthreads();
    }
    float sdot = red[0];
    float cc1 = g_cc1;
    for (int r = wid * 32; r < wid * 32 + 32; r++) {
        float a = 0.f;
        for (int j = lane; j < CCH; j += 32) a += g_G[b][r][j] * r1s[j];
#pragma unroll
        for (int o = 16; o > 0; o >>= 1) a += __shfl_down_sync(0xffffffffu, a, o);
        if (lane == 0) t2vs[r] = a;
    }
    __syncthreads();
    for (int r = wid * 32; r < wid * 32 + 32; r++) {
        float a = 0.f, u = 0.f;
        for (int j = lane; j < CCH; j += 32) {
            float av = g_A[2][r][j];
            a += av * t2vs[j];
            u += av * ss[j];
        }
#pragma unroll
        for (int o = 16; o > 0; o >>= 1) {
            a += __shfl_down_sync(0xffffffffu, a, o);
            u += __shfl_down_sync(0xffffffffu, u, o);
        }
        if (lane == 0) {
            float cv = g_cvec[2][r];
            g_d[b][r] = SCALE * (a + u * cc1 + cv * (sdot + 4096.0f * cc1));
        }
    }
}

// ================= shared smem layout for 128x128 K=256 bf16 hi/lo GEMMs ========
#define OB_STRIDE 272
#define OU_AH 0
#define OU_AL 10240
#define OU_BH 20480
#define OU_BL (20480 + 32 * OB_STRIDE)
#define OU_BUF (20480 + 2 * 32 * OB_STRIDE)   // 37888
#define OU_SMEM (2 * OU_BUF)                  // 75776

// ================= T2 = G * R (bf16 hi/lo, per batch) =================
__global__ __launch_bounds__(256) void t2_mma_kernel() {
    extern __shared__ char smem[];
    uint32_t sb = smem_u32(smem);
    int t = threadIdx.x, lane = t & 31, wid = t >> 5;
    int nt = blockIdx.x, mt = blockIdx.y, b = blockIdx.z;
    int wm = (wid >> 2) * 64, wn = (wid & 3) * 32;
    const __nv_bfloat16* Ah = &g_Gh[b][mt * 128][0];
    const __nv_bfloat16* Al = &g_Gl[b][mt * 128][0];
    const __nv_bfloat16* Bh = &g_Rh[0][nt * 128];
    const __nv_bfloat16* Bl = &g_Rl[0][nt * 128];

    float acc[4][4][4] = {};

    auto stage = [&](int buf, int kk) {
        uint32_t base = sb + buf * OU_BUF;
#pragma unroll
        for (int i = t; i < 512; i += 256) {
            int r = i >> 2, c = i & 3;
            CPA16(base + OU_AH + r * 80 + c * 16, (const char*)(Ah + (long)r * CCH + kk + c * 8));
            CPA16(base + OU_AL + r * 80 + c * 16, (const char*)(Al + (long)r * CCH + kk + c * 8));
        }
#pragma unroll
        for (int i = t; i < 512; i += 256) {
            int r = i >> 4, c = i & 15;
            CPA16(base + OU_BH + r * OB_STRIDE + c * 16, (const char*)(Bh + (long)(kk + r) * CCH + c * 8));
            CPA16(base + OU_BL + r * OB_STRIDE + c * 16, (const char*)(Bl + (long)(kk + r) * CCH + c * 8));
        }
    };

    stage(0, 0);
    CPA_COMMIT();
    const int S = 8;
    for (int s = 0; s < S; s++) {
        if (s + 1 < S) { stage((s + 1) & 1, (s + 1) * 32); CPA_COMMIT(); CPA_WAIT1(); }
        else CPA_WAIT0();
        __syncthreads();
        uint32_t base = sb + (s & 1) * OU_BUF;
#pragma unroll
        for (int ks = 0; ks < 32; ks += 16) {
            uint32_t afh[4][4], afl[4][4], bfh[4][2], bfl[4][2];
#pragma unroll
            for (int i = 0; i < 4; i++) {
                uint32_t ao = (wm + i * 16 + (lane & 15)) * 80 + ks * 2 + (lane >> 4) * 16;
                ldsm4(afh[i], base + OU_AH + ao);
                ldsm4(afl[i], base + OU_AL + ao);
            }
#pragma unroll
            for (int j = 0; j < 2; j++) {
                uint32_t bo = (ks + (lane & 15)) * OB_STRIDE + (wn + j * 16 + (lane >> 4) * 8) * 2;
                uint32_t r[4];
                ldsm4t(r, base + OU_BH + bo);
                bfh[2 * j][0] = r[0]; bfh[2 * j][1] = r[1];
                bfh[2 * j + 1][0] = r[2]; bfh[2 * j + 1][1] = r[3];
                ldsm4t(r, base + OU_BL + bo);
                bfl[2 * j][0] = r[0]; bfl[2 * j][1] = r[1];
                bfl[2 * j + 1][0] = r[2]; bfl[2 * j + 1][1] = r[3];
            }
#pragma unroll
            for (int i = 0; i < 4; i++)
#pragma unroll
                for (int j = 0; j < 4; j++) {
                    mma_bf16(acc[i][j], afh[i], bfh[j]);
                    mma_bf16(acc[i][j], afh[i], bfl[j]);
                    mma_bf16(acc[i][j], afl[i], bfh[j]);
                }
        }
        __syncthreads();
    }

#pragma unroll
    for (int i = 0; i < 4; i++) {
        int m = mt * 128 + wm + i * 16 + (lane >> 2);
#pragma unroll
        for (int j = 0; j < 4; j++) {
            int n = nt * 128 + wn + j * 8 + (lane & 3) * 2;
            split_store(&g_T2h[b][m][n],     &g_T2l[b][m][n],     acc[i][j][0]);
            split_store(&g_T2h[b][m][n + 1], &g_T2l[b][m][n + 1], acc[i][j][1]);
            split_store(&g_T2h[b][m + 8][n],     &g_T2l[b][m + 8][n],     acc[i][j][2]);
            split_store(&g_T2h[b][m + 8][n + 1], &g_T2l[b][m + 8][n + 1], acc[i][j][3]);
        }
    }
}

// ================= P = SCALE(Av*T2 + rank-1) -> bf16 hi/lo =================
__global__ __launch_bounds__(256) void p_mma_kernel() {
    extern __shared__ char smem[];
    uint32_t sb = smem_u32(smem);
    __shared__ float ss[CCH], us[128], w2s[128], a1s[128], cvs[128];
    int t = threadIdx.x, lane = t & 31, wid = t >> 5;
    int nt = blockIdx.x, mt = blockIdx.y, b = blockIdx.z;
    int wm = (wid >> 2) * 64, wn = (wid & 3) * 32;
    int mtBase = mt * 128, ntBase = nt * 128;
    const __nv_bfloat16* Ah = &g_Avh[mtBase][0];
    const __nv_bfloat16* Al = &g_Avl[mtBase][0];
    const __nv_bfloat16* Bh = &g_T2h[b][0][ntBase];
    const __nv_bfloat16* Bl = &g_T2l[b][0][ntBase];

    float acc[4][4][4] = {};

    auto stage = [&](int buf, int kk) {
        uint32_t base = sb + buf * OU_BUF;
#pragma unroll
        for (int i = t; i < 512; i += 256) {
            int r = i >> 2, c = i & 3;
            CPA16(base + OU_AH + r * 80 + c * 16, (const char*)(Ah + (long)r * CCH + kk + c * 8));
            CPA16(base + OU_AL + r * 80 + c * 16, (const char*)(Al + (long)r * CCH + kk + c * 8));
        }
#pragma unroll
        for (int i = t; i < 512; i += 256) {
            int r = i >> 4, c = i & 15;
            CPA16(base + OU_BH + r * OB_STRIDE + c * 16, (const char*)(Bh + (long)(kk + r) * CCH + c * 8));
            CPA16(base + OU_BL + r * OB_STRIDE + c * 16, (const char*)(Bl + (long)(kk + r) * CCH + c * 8));
        }
    };

    stage(0, 0);
    CPA_COMMIT();

    // prologue (hidden under first cp.async): u = Av*s rows, w2 = R^T s cols
    ss[t] = g_s[b][t];
    __syncthreads();
    for (int r = wid * 16; r < wid * 16 + 16; r++) {
        float a = 0.f;
        for (int j = lane; j < CCH; j += 32) a += g_A[2][mtBase + r][j] * ss[j];
#pragma unroll
        for (int o = 16; o > 0; o >>= 1) a += __shfl_down_sync(0xffffffffu, a, o);
        if (lane == 0) us[r] = a;
    }
    if (t < 128) {
        float a = 0.f;
        for (int k = 0; k < CCH; k++) a += g_R[k][ntBase + t] * ss[k];
        w2s[t] = a;
        a1s[t] = g_a1[ntBase + t];
        cvs[t] = g_cvec[2][mtBase + t];
    }

    const int S = 8;
    for (int s = 0; s < S; s++) {
        if (s + 1 < S) { stage((s + 1) & 1, (s + 1) * 32); CPA_COMMIT(); CPA_WAIT1(); }
        else CPA_WAIT0();
        __syncthreads();
        uint32_t base = sb + (s & 1) * OU_BUF;
#pragma unroll
        for (int ks = 0; ks < 32; ks += 16) {
            uint32_t afh[4][4], afl[4][4], bfh[4][2], bfl[4][2];
#pragma unroll
            for (int i = 0; i < 4; i++) {
                uint32_t ao = (wm + i * 16 + (lane & 15)) * 80 + ks * 2 + (lane >> 4) * 16;
                ldsm4(afh[i], base + OU_AH + ao);
                ldsm4(afl[i], base + OU_AL + ao);
            }
#pragma unroll
            for (int j = 0; j < 2; j++) {
                uint32_t bo = (ks + (lane & 15)) * OB_STRIDE + (wn + j * 16 + (lane >> 4) * 8) * 2;
                uint32_t r[4];
                ldsm4t(r, base + OU_BH + bo);
                bfh[2 * j][0] = r[0]; bfh[2 * j][1] = r[1];
                bfh[2 * j + 1][0] = r[2]; bfh[2 * j + 1][1] = r[3];
                ldsm4t(r, base + OU_BL + bo);
                bfl[2 * j][0] = r[0]; bfl[2 * j][1] = r[1];
                bfl[2 * j + 1][0] = r[2]; bfl[2 * j + 1][1] = r[3];
            }
#pragma unroll
            for (int i = 0; i < 4; i++)
#pragma unroll
                for (int j = 0; j < 4; j++) {
                    mma_bf16(acc[i][j], afh[i], bfh[j]);
                    mma_bf16(acc[i][j], afh[i], bfl[j]);
                    mma_bf16(acc[i][j], afl[i], bfh[j]);
                }
        }
        __syncthreads();
    }

#pragma unroll
    for (int i = 0; i < 4; i++) {
        int rl = wm + i * 16 + (lane >> 2);
        int m = mtBase + rl;
        float u0 = us[rl], u1 = us[rl + 8];
        float cv0 = cvs[rl], cv1 = cvs[rl + 8];
#pragma unroll
        for (int j = 0; j < 4; j++) {
            int cl = wn + j * 8 + (lane & 3) * 2;
            int n = ntBase + cl;
            float a10 = a1s[cl], a11 = a1s[cl + 1];
            float w20 = w2s[cl], w21 = w2s[cl + 1];
            float v00 = SCALE * (acc[i][j][0] + u0 * a10 + cv0 * w20 + 4096.0f * cv0 * a10);
            float v01 = SCALE * (acc[i][j][1] + u0 * a11 + cv0 * w21 + 4096.0f * cv0 * a11);
            float v10 = SCALE * (acc[i][j][2] + u1 * a10 + cv1 * w20 + 4096.0f * cv1 * a10);
            float v11 = SCALE * (acc[i][j][3] + u1 * a11 + cv1 * w21 + 4096.0f * cv1 * a11);
            split_store(&g_Ph[b][m][n],     &g_Pl[b][m][n],     v00);
            split_store(&g_Ph[b][m][n + 1], &g_Pl[b][m][n + 1], v01);
            split_store(&g_Ph[b][m + 8][n],     &g_Pl[b][m + 8][n],     v10);
            split_store(&g_Ph[b][m + 8][n + 1], &g_Pl[b][m + 8][n + 1], v11);
        }
    }
}

// ================= out = Ph Xh + Ph Xl + Pl Xh (+d) =================
__global__ __launch_bounds__(256) void out_mma_kernel(float* __restrict__ out) {
    extern __shared__ char smem[];
    uint32_t sb = smem_u32(smem);
    int t = threadIdx.x, lane = t & 31, wid = t >> 5;
    int pt = blockIdx.x, mt = blockIdx.y, b = blockIdx.z;
    int wm = (wid >> 2) * 64, wn = (wid & 3) * 32;
    const __nv_bfloat16* Ah = &g_Ph[b][mt * 128][0];
    const __nv_bfloat16* Al = &g_Pl[b][mt * 128][0];
    const __nv_bfloat16* Bh = &g_xh[b][0][pt * 128];
    const __nv_bfloat16* Bl = &g_xl[b][0][pt * 128];

    float acc[4][4][4] = {};

    auto stage = [&](int buf, int kk) {
        uint32_t base = sb + buf * OU_BUF;
#pragma unroll
        for (int i = t; i < 512; i += 256) {
            int r = i >> 2, c = i & 3;
            CPA16(base + OU_AH + r * 80 + c * 16, (const char*)(Ah + (long)r * CCH + kk + c * 8));
            CPA16(base + OU_AL + r * 80 + c * 16, (const char*)(Al + (long)r * CCH + kk + c * 8));
        }
#pragma unroll
        for (int i = t; i < 512; i += 256) {
            int r = i >> 4, c = i & 15;
            CPA16(base + OU_BH + r * OB_STRIDE + c * 16, (const char*)(Bh + (long)(kk + r) * HWN + c * 8));
            CPA16(base + OU_BL + r * OB_STRIDE + c * 16, (const char*)(Bl + (long)(kk + r) * HWN + c * 8));
        }
    };

    stage(0, 0);
    CPA_COMMIT();
    const int S = 8;
    for (int s = 0; s < S; s++) {
        if (s + 1 < S) { stage((s + 1) & 1, (s + 1) * 32); CPA_COMMIT(); CPA_WAIT1(); }
        else CPA_WAIT0();
        __syncthreads();
        uint32_t base = sb + (s & 1) * OU_BUF;
#pragma unroll
        for (int ks = 0; ks < 32; ks += 16) {
            uint32_t afh[4][4], afl[4][4], bfh[4][2], bfl[4][2];
#pragma unroll
            for (int i = 0; i < 4; i++) {
                uint32_t ao = (wm + i * 16 + (lane & 15)) * 80 + ks * 2 + (lane >> 4) * 16;
                ldsm4(afh[i], base + OU_AH + ao);
                ldsm4(afl[i], base + OU_AL + ao);
            }
#pragma unroll
            for (int j = 0; j < 2; j++) {
                uint32_t bo = (ks + (lane & 15)) * OB_STRIDE + (wn + j * 16 + (lane >> 4) * 8) * 2;
                uint32_t r[4];
                ldsm4t(r, base + OU_BH + bo);
                bfh[2 * j][0] = r[0]; bfh[2 * j][1] = r[1];
                bfh[2 * j + 1][0] = r[2]; bfh[2 * j + 1][1] = r[3];
                ldsm4t(r, base + OU_BL + bo);
                bfl[2 * j][0] = r[0]; bfl[2 * j][1] = r[1];
                bfl[2 * j + 1][0] = r[2]; bfl[2 * j + 1][1] = r[3];
            }
#pragma unroll
            for (int i = 0; i < 4; i++)
#pragma unroll
                for (int j = 0; j < 4; j++) {
                    mma_bf16(acc[i][j], afh[i], bfh[j]);
                    mma_bf16(acc[i][j], afh[i], bfl[j]);
                    mma_bf16(acc[i][j], afl[i], bfh[j]);
                }
        }
        __syncthreads();
    }

#pragma unroll
    for (int i = 0; i < 4; i++) {
        int m = mt * 128 + wm + i * 16 + (lane >> 2);
        float d0 = g_d[b][m], d1 = g_d[b][m + 8];
        float* O0 = out + ((long)(b * CCH + m)) * HWN + pt * 128;
        float* O1 = O0 + 8L * HWN;
#pragma unroll
        for (int j = 0; j < 4; j++) {
            int n = wn + j * 8 + (lane & 3) * 2;
            *(float2*)(O0 + n) = make_float2(acc[i][j][0] + d0, acc[i][j][1] + d0);
            *(float2*)(O1 + n) = make_float2(acc[i][j][2] + d1, acc[i][j][3] + d1);
        }
    }
}

// ================= launch =================
extern "C" void kernel_launch(void* const* d_in, const int* in_sizes, int n_in,
                              void* d_out, int out_size) {
    const float* x = (const float*)d_in[0];

    static bool attr_done = false;
    if (!attr_done) {
        cudaFuncSetAttribute(gram_mma_kernel, cudaFuncAttributeMaxDynamicSharedMemorySize, GR_SMEM);
        cudaFuncSetAttribute(t2_mma_kernel,   cudaFuncAttributeMaxDynamicSharedMemorySize, OU_SMEM);
        cudaFuncSetAttribute(p_mma_kernel,    cudaFuncAttributeMaxDynamicSharedMemorySize, OU_SMEM);
        cudaFuncSetAttribute(out_mma_kernel,  cudaFuncAttributeMaxDynamicSharedMemorySize, OU_SMEM);
        attr_done = true;
    }

    prep_kernel<<<dim3(CCH, BATCH), 256>>>(x);
    gram_mma_kernel<<<dim3(4, 4, BATCH), 512, GR_SMEM>>>();
    reduceG_kernel<<<dim3(8, 8, BATCH), 256>>>();
    cov_kernel<<<CCH, 256>>>();
    proj_kernel<<<dim3(CCH, 3), 256>>>(
        (const float*)d_in[1], (const float*)d_in[2], (const float*)d_in[3], (const float*)d_in[4],
        (const float*)d_in[5], (const float*)d_in[6], (const float*)d_in[7], (const float*)d_in[8],
        (const float*)d_in[9], (const float*)d_in[10], (const float*)d_in[11], (const float*)d_in[12]);
    rk_kernel<<<dim3(8, 8), 256>>>();
    vec_kernel<<<BATCH, 256>>>();
    t2_mma_kernel<<<dim3(2, 2, BATCH), 256, OU_SMEM>>>();
    p_mma_kernel<<<dim3(2, 2, BATCH), 256, OU_SMEM>>>();
    out_mma_kernel<<<dim3(32, 2, BATCH), 256, OU_SMEM>>>((float*)d_out);
}

// round 10
// speedup vs baseline: 1.0560x; 1.0560x over previous
#include <cuda_runtime.h>
#include <cuda_bf16.h>
#include <cstdint>

// PatchAttentionLayer on GB300 (sm_103 baseline PTX path).
// BN folded into affine maps; attention via associativity (no NxN map).
// Big GEMMs on mma.sync bf16 hi/lo. R10: single persistent mega-kernel with
// SELF-RESETTING sense-reversal grid barriers (no host reset needed);
// out_mma is the only other launch. Launch count 9 -> 2.

#define CCH 256
#define BATCH 8
#define HWN 4096
#define EPS_BN 1e-5f
#define INV_NPOS (1.0f / 32768.0f)
#define SCALE 0.125f
#define NCTA 128

// ================= device scratch =================
__device__ __nv_bfloat16 g_xh[BATCH][CCH][HWN];
__device__ __nv_bfloat16 g_xl[BATCH][CCH][HWN];
__device__ float g_S1p[4][BATCH][CCH][CCH];
__device__ float g_S2p[4][BATCH][CCH][CCH];
__device__ float g_s[BATCH][CCH];
__device__ float g_mean[CCH];
__device__ float g_Cov[CCH][CCH];
__device__ float g_A[3][CCH][CCH];
__device__ float g_cvec[3][CCH];
__device__ float g_G[BATCH][CCH][CCH];
__device__ float g_T1[BATCH][CCH][CCH];
__device__ float g_M[BATCH][CCH][CCH];
__device__ float g_d[BATCH][CCH];
__device__ __nv_bfloat16 g_Ph[BATCH][CCH][CCH];
__device__ __nv_bfloat16 g_Pl[BATCH][CCH][CCH];
// self-resetting barrier state (zero-initialized at module load; counters
// always return to 0 after each barrier completes, so replays stay correct)
__device__ unsigned g_barc[8];
__device__ unsigned g_gen[8];

// ================= helpers =================
__device__ __forceinline__ uint32_t smem_u32(const void* p) {
    uint32_t a;
    asm("{ .reg .u64 t; cvta.to.shared.u64 t, %1; cvt.u32.u64 %0, t; }" : "=r"(a) : "l"(p));
    return a;
}
__device__ __forceinline__ void ldsm4(uint32_t* r, uint32_t a) {
    asm volatile("ldmatrix.sync.aligned.m8n8.x4.shared.b16 {%0,%1,%2,%3}, [%4];"
                 : "=r"(r[0]), "=r"(r[1]), "=r"(r[2]), "=r"(r[3]) : "r"(a));
}
__device__ __forceinline__ void ldsm4t(uint32_t* r, uint32_t a) {
    asm volatile("ldmatrix.sync.aligned.m8n8.x4.trans.shared.b16 {%0,%1,%2,%3}, [%4];"
                 : "=r"(r[0]), "=r"(r[1]), "=r"(r[2]), "=r"(r[3]) : "r"(a));
}
__device__ __forceinline__ void mma_bf16(float* c, const uint32_t* a, const uint32_t* b) {
    asm volatile(
        "mma.sync.aligned.m16n8k16.row.col.f32.bf16.bf16.f32 "
        "{%0,%1,%2,%3},{%4,%5,%6,%7},{%8,%9},{%0,%1,%2,%3};"
        : "+f"(c[0]), "+f"(c[1]), "+f"(c[2]), "+f"(c[3])
        : "r"(a[0]), "r"(a[1]), "r"(a[2]), "r"(a[3]), "r"(b[0]), "r"(b[1]));
}
#define CPA16(dst, src) asm volatile("cp.async.cg.shared.global [%0], [%1], 16;" :: "r"(dst), "l"(src))
#define CPA_COMMIT()    asm volatile("cp.async.commit_group;")
#define CPA_WAIT1()     asm volatile("cp.async.wait_group 1;")
#define CPA_WAIT0()     asm volatile("cp.async.wait_group 0;")

__device__ __forceinline__ void split_store(__nv_bfloat16* ph, __nv_bfloat16* pl, float v) {
    __nv_bfloat16 h = __float2bfloat16(v);
    *ph = h;
    *pl = __float2bfloat16(v - __bfloat162float(h));
}

// self-resetting sense-reversal grid barrier (all NCTA CTAs co-resident)
__device__ __forceinline__ void grid_bar(int k) {
    __syncthreads();
    if (threadIdx.x == 0) {
        __threadfence();
        unsigned gen = *((volatile unsigned*)&g_gen[k]);
        unsigned arrived = atomicAdd(&g_barc[k], 1u);
        if (arrived == NCTA - 1) {
            g_barc[k] = 0;           // reset for next use (next launch/replay)
            __threadfence();
            atomicAdd(&g_gen[k], 1u);  // release
        } else {
            while (*((volatile unsigned*)&g_gen[k]) == gen) { __nanosleep(32); }
        }
        __threadfence();
    }
    __syncthreads();
}

// fp32 glue GEMM micro-kernel
__device__ __forceinline__ void mma16f(const float (*As)[65], const float (*Bs)[65],
                                       int ty, int tx, float acc[4][4]) {
#pragma unroll
    for (int kk = 0; kk < 16; kk++) {
        float a[4], b[4];
#pragma unroll
        for (int i = 0; i < 4; i++) a[i] = As[kk][ty * 4 + i];
#pragma unroll
        for (int j = 0; j < 4; j++) b[j] = Bs[kk][tx * 4 + j];
#pragma unroll
        for (int i = 0; i < 4; i++)
#pragma unroll
            for (int j = 0; j < 4; j++) acc[i][j] += a[i] * b[j];
    }
}

// ================= mega kernel: prep..p in one launch =================
#define GR_TILE 10240
#define GR_BUF  (3 * GR_TILE)
#define GR_SMEM (2 * GR_BUF)   // 61440 dynamic

__global__ __launch_bounds__(512) void mega_kernel(
    const float* __restrict__ x,
    const float* __restrict__ Wq, const float* __restrict__ bq, const float* __restrict__ gq, const float* __restrict__ beq,
    const float* __restrict__ Wk, const float* __restrict__ bk, const float* __restrict__ gk, const float* __restrict__ bek,
    const float* __restrict__ Wv, const float* __restrict__ bv, const float* __restrict__ gv, const float* __restrict__ bev) {
    extern __shared__ char smem[];
    __shared__ float As[16][65], Bs[16][65];
    __shared__ float tt[32][33];
    __shared__ float ws2[2][CCH], s1[512], s2[512];
    __shared__ float ac_sh[2][2], mc_sh[2];
    __shared__ float ss[CCH], su[64], sw[64], cqs[CCH];
    __shared__ float wred[16];

    int t = threadIdx.x, cta = blockIdx.x;
    int lane = t & 31, wid = t >> 5;

    // -------- P0: prep (split x -> bf16 hi/lo; channel sums) --------
    {
        for (int q = 0; q < 16; q++) {
            int ch = cta * 16 + q;
            int b = ch >> 8, c = ch & 255;
            const float4* src = (const float4*)(x + ((long)(b * CCH + c)) * HWN);
            __nv_bfloat162* dh = (__nv_bfloat162*)&g_xh[b][c][0];
            __nv_bfloat162* dl = (__nv_bfloat162*)&g_xl[b][c][0];
            float s = 0.f;
            for (int i = t; i < 1024; i += 512) {
                float4 v = src[i];
                s += (v.x + v.y) + (v.z + v.w);
                __nv_bfloat16 h0 = __float2bfloat16(v.x), h1 = __float2bfloat16(v.y);
                __nv_bfloat16 h2 = __float2bfloat16(v.z), h3 = __float2bfloat16(v.w);
                __nv_bfloat162 hh0; hh0.x = h0; hh0.y = h1;
                __nv_bfloat162 hh1; hh1.x = h2; hh1.y = h3;
                __nv_bfloat162 ll0, ll1;
                ll0.x = __float2bfloat16(v.x - __bfloat162float(h0));
                ll0.y = __float2bfloat16(v.y - __bfloat162float(h1));
                ll1.x = __float2bfloat16(v.z - __bfloat162float(h2));
                ll1.y = __float2bfloat16(v.w - __bfloat162float(h3));
                dh[2 * i] = hh0; dh[2 * i + 1] = hh1;
                dl[2 * i] = ll0; dl[2 * i + 1] = ll1;
            }
#pragma unroll
            for (int o = 16; o > 0; o >>= 1) s += __shfl_down_sync(0xffffffffu, s, o);
            if (lane == 0) wred[wid] = s;
            __syncthreads();
            if (t == 0) {
                float a = 0.f;
#pragma unroll
                for (int w = 0; w < 16; w++) a += wred[w];
                g_s[b][c] = a;
            }
            __syncthreads();
        }
    }
    grid_bar(0);

    // -------- P1: gram  S1 = H H^T, S2 = H L^T (bf16 mma, split-K) --------
    {
        uint32_t sb = smem_u32(smem);
        int split = cta & 3, tileId = (cta >> 2) & 3, b = cta >> 4;
        int mt = tileId >> 1, nt = tileId & 1;
        const __nv_bfloat16* Ag  = &g_xh[b][mt * 128][0];
        const __nv_bfloat16* BgH = &g_xh[b][nt * 128][0];
        const __nv_bfloat16* BgL = &g_xl[b][nt * 128][0];
        int k0 = split * 1024;
        int grp = wid >> 3, w8 = wid & 7;
        int wm = (w8 >> 2) * 64, wn = (w8 & 3) * 32;

        float acc[4][4][4] = {};

        auto stage = [&](int buf, int kk) {
            uint32_t base = sb + buf * GR_BUF;
            int r = t >> 2, c = t & 3;
            long go = (long)r * HWN + kk + c * 8;
            uint32_t so = r * 80 + c * 16;
            CPA16(base + so,               (const char*)(Ag + go));
            CPA16(base + GR_TILE + so,     (const char*)(BgH + go));
            CPA16(base + 2 * GR_TILE + so, (const char*)(BgL + go));
        };

        stage(0, k0);
        CPA_COMMIT();
        const int S = 32;
        for (int s = 0; s < S; s++) {
            if (s + 1 < S) { stage((s + 1) & 1, k0 + (s + 1) * 32); CPA_COMMIT(); CPA_WAIT1(); }
            else CPA_WAIT0();
            __syncthreads();
            uint32_t aBase = sb + (s & 1) * GR_BUF;
            uint32_t bBase = aBase + GR_TILE + grp * GR_TILE;
#pragma unroll
            for (int ks = 0; ks < 32; ks += 16) {
                uint32_t af[4][4], bf[4][2];
#pragma unroll
                for (int i = 0; i < 4; i++)
                    ldsm4(af[i], aBase + (wm + i * 16 + (lane & 15)) * 80 + ks * 2 + (lane >> 4) * 16);
#pragma unroll
                for (int j = 0; j < 2; j++) {
                    uint32_t r[4];
                    ldsm4(r, bBase + (wn + j * 16 + (lane & 15)) * 80 + ks * 2 + (lane >> 4) * 16);
                    bf[2 * j][0] = r[0]; bf[2 * j][1] = r[2];
                    bf[2 * j + 1][0] = r[1]; bf[2 * j + 1][1] = r[3];
                }
#pragma unroll
                for (int i = 0; i < 4; i++)
#pragma unroll
                    for (int j = 0; j < 4; j++) mma_bf16(acc[i][j], af[i], bf[j]);
            }
            __syncthreads();
        }

        float* dst = grp ? &g_S2p[split][b][0][0] : &g_S1p[split][b][0][0];
#pragma unroll
        for (int i = 0; i < 4; i++) {
            int m = mt * 128 + wm + i * 16 + (lane >> 2);
#pragma unroll
            for (int j = 0; j < 4; j++) {
                int n = nt * 128 + wn + j * 8 + (lane & 3) * 2;
                *(float2*)(dst + (long)m * CCH + n) = make_float2(acc[i][j][0], acc[i][j][1]);
                *(float2*)(dst + (long)(m + 8) * CCH + n) = make_float2(acc[i][j][2], acc[i][j][3]);
            }
        }
    }
    grid_bar(1);

    // -------- P2: reduceG  G = sum_sp(S1+S2) + (sum_sp S2)^T --------
    {
        int lx = t & 31, ly = t >> 5;   // ly 0..15
        for (int q = 0; q < 4; q++) {
            int u = cta * 4 + q;
            int jt = (u & 7) * 32, it = ((u >> 3) & 7) * 32, b = u >> 6;
            __syncthreads();
            for (int r = ly; r < 32; r += 16) {
                float s = 0.f;
#pragma unroll
                for (int sp = 0; sp < 4; sp++) s += g_S2p[sp][b][jt + r][it + lx];
                tt[r][lx] = s;
            }
            __syncthreads();
            for (int r = ly; r < 32; r += 16) {
                float s = tt[lx][r];
#pragma unroll
                for (int sp = 0; sp < 4; sp++)
                    s += g_S1p[sp][b][it + r][jt + lx] + g_S2p[sp][b][it + r][jt + lx];
                g_G[b][it + r][jt + lx] = s;
            }
        }
    }
    grid_bar(2);

    // -------- P3: cov + mean --------
    {
        int half = t >> 8, tl = t & 255;
        int c = cta * 2 + half;
        float mt_ = 0.f;
#pragma unroll
        for (int b = 0; b < BATCH; b++) mt_ += g_s[b][tl];
        mt_ *= INV_NPOS;
        if (tl == c) mc_sh[half] = mt_;
        __syncthreads();
        float s = 0.f;
#pragma unroll
        for (int b = 0; b < BATCH; b++) s += g_G[b][c][tl];
        g_Cov[c][tl] = s * INV_NPOS - mc_sh[half] * mt_;
        if (c == 0) g_mean[tl] = mt_;
    }
    grid_bar(3);

    // -------- P4: proj (BN fold) -- 6 units per CTA, 2 at a time --------
    {
        int half = t >> 8, tl = t & 255;
        for (int rr = 0; rr < 3; rr++) {
            int pu = cta * 6 + rr * 2 + half;  // 0..767
            int tp = pu >> 8, o = pu & 255;
            const float *W, *bb, *gg, *be;
            if (tp == 0) { W = Wq; bb = bq; gg = gq; be = beq; }
            else if (tp == 1) { W = Wk; bb = bk; gg = gk; be = bek; }
            else { W = Wv; bb = bv; gg = gv; be = bev; }
            ws2[half][tl] = W[o * CCH + tl];
            __syncthreads();
            float col = 0.f;
            for (int c = 0; c < CCH; c++) col += ws2[half][c] * g_Cov[c][tl];
            s1[t] = col * ws2[half][tl];
            s2[t] = ws2[half][tl] * g_mean[tl];
            __syncthreads();
            for (int off = 128; off > 0; off >>= 1) {
                if (tl < off) { s1[t] += s1[t + off]; s2[t] += s2[t + off]; }
                __syncthreads();
            }
            if (tl == 0) {
                float var = s1[half * 256];
                float mu = s2[half * 256] + bb[o];
                float a = gg[o] * rsqrtf(var + EPS_BN);
                ac_sh[half][0] = a;
                ac_sh[half][1] = (bb[o] - mu) * a + be[o];
            }
            __syncthreads();
            g_A[tp][o][tl] = ac_sh[half][0] * ws2[half][tl];
            if (tl == 0) g_cvec[tp][o] = ac_sh[half][1];
            __syncthreads();
        }
    }
    grid_bar(4);

    // -------- P5: T1 = G * Ak^T (fp32, threads 0-255 active) --------
    {
        bool act = (t < 256);
        int tl = t & 255, tx = tl & 15, ty = tl >> 4;
        int r = tl >> 2, kseg = (tl & 3) * 4;
        int colBase = (cta & 3) * 64, rowBase = ((cta >> 2) & 3) * 64, b = cta >> 4;
        float acc[4][4] = {};
        const float* A = &g_G[b][0][0];
        const float* B = &g_A[1][0][0];
        for (int k0 = 0; k0 < CCH; k0 += 16) {
            if (act) {
                float4 av = *(const float4*)(A + (rowBase + r) * CCH + k0 + kseg);
                float4 bv = *(const float4*)(B + (colBase + r) * CCH + k0 + kseg);
                As[kseg + 0][r] = av.x; As[kseg + 1][r] = av.y; As[kseg + 2][r] = av.z; As[kseg + 3][r] = av.w;
                Bs[kseg + 0][r] = bv.x; Bs[kseg + 1][r] = bv.y; Bs[kseg + 2][r] = bv.z; Bs[kseg + 3][r] = bv.w;
            }
            __syncthreads();
            if (act) mma16f(As, Bs, ty, tx, acc);
            __syncthreads();
        }
        if (act) {
#pragma unroll
            for (int i = 0; i < 4; i++)
#pragma unroll
                for (int j = 0; j < 4; j++)
                    g_T1[b][rowBase + ty * 4 + i][colBase + tx * 4 + j] = acc[i][j];
        }
    }
    grid_bar(5);

    // -------- P6: M = Av*T1 + rank-1 --------
    {
        bool act = (t < 256);
        int tl = t & 255, tx = tl & 15, ty = tl >> 4;
        int ar = tl >> 2, akseg = (tl & 3) * 4;
        int bkk = tl >> 4, bcc = (tl & 15) * 4;
        int colBase = (cta & 3) * 64, rowBase = ((cta >> 2) & 3) * 64, b = cta >> 4;
        if (act) ss[tl] = g_s[b][tl];
        __syncthreads();
        if (t < 64) {
            float a = 0.f;
            const float* row = &g_A[2][rowBase + t][0];
            for (int c = 0; c < CCH; c++) a += row[c] * ss[c];
            su[t] = a;
        } else if (t < 128) {
            int j = t - 64;
            float a = 0.f;
            const float* row = &g_A[1][colBase + j][0];
            for (int c = 0; c < CCH; c++) a += row[c] * ss[c];
            sw[j] = a;
        }
        float acc[4][4] = {};
        const float* A = &g_A[2][0][0];
        const float* B = &g_T1[b][0][0];
        for (int k0 = 0; k0 < CCH; k0 += 16) {
            if (act) {
                float4 av = *(const float4*)(A + (rowBase + ar) * CCH + k0 + akseg);
                float4 bv = *(const float4*)(B + (k0 + bkk) * CCH + colBase + bcc);
                As[akseg + 0][ar] = av.x; As[akseg + 1][ar] = av.y; As[akseg + 2][ar] = av.z; As[akseg + 3][ar] = av.w;
                Bs[bkk][bcc + 0] = bv.x; Bs[bkk][bcc + 1] = bv.y; Bs[bkk][bcc + 2] = bv.z; Bs[bkk][bcc + 3] = bv.w;
            }
            __syncthreads();
            if (act) mma16f(As, Bs, ty, tx, acc);
            __syncthreads();
        }
        if (act) {
#pragma unroll
            for (int i = 0; i < 4; i++) {
                int ri = rowBase + ty * 4 + i;
                float u = su[ty * 4 + i], cv = g_cvec[2][ri];
#pragma unroll
                for (int j = 0; j < 4; j++) {
                    int cj = colBase + tx * 4 + j;
                    float ck = g_cvec[1][cj];
                    g_M[b][ri][cj] = acc[i][j] + u * ck + cv * sw[tx * 4 + j] + 4096.0f * cv * ck;
                }
            }
        }
    }
    grid_bar(6);

    // -------- P7: P = SCALE*M*Aq -> bf16 hi/lo; d fused --------
    {
        bool act = (t < 256);
        int tl = t & 255, tx = tl & 15, ty = tl >> 4;
        int ar = tl >> 2, akseg = (tl & 3) * 4;
        int bkk = tl >> 4, bcc = (tl & 15) * 4;
        int colBase = (cta & 3) * 64, rowBase = ((cta >> 2) & 3) * 64, b = cta >> 4;
        if (act) cqs[tl] = g_cvec[0][tl];
        float acc[4][4] = {};
        float dacc[4] = {};
        const float* A = &g_M[b][0][0];
        const float* B = &g_A[0][0][0];
        for (int k0 = 0; k0 < CCH; k0 += 16) {
            if (act) {
                float4 av = *(const float4*)(A + (rowBase + ar) * CCH + k0 + akseg);
                float4 bv = *(const float4*)(B + (k0 + bkk) * CCH + colBase + bcc);
                As[akseg + 0][ar] = av.x; As[akseg + 1][ar] = av.y; As[akseg + 2][ar] = av.z; As[akseg + 3][ar] = av.w;
                Bs[bkk][bcc + 0] = bv.x; Bs[bkk][bcc + 1] = bv.y; Bs[bkk][bcc + 2] = bv.z; Bs[bkk][bcc + 3] = bv.w;
            }
            __syncthreads();
            if (act) {
                mma16f(As, Bs, ty, tx, acc);
                if (tx == 0) {
#pragma unroll
                    for (int kk = 0; kk < 16; kk++) {
                        float cq = cqs[k0 + kk];
#pragma unroll
                        for (int i = 0; i < 4; i++) dacc[i] += As[kk][ty * 4 + i] * cq;
                    }
                }
            }
            __syncthreads();
        }
        if (act) {
#pragma unroll
            for (int i = 0; i < 4; i++) {
                int ri = rowBase + ty * 4 + i;
#pragma unroll
                for (int j = 0; j < 4; j++) {
                    int cj = colBase + tx * 4 + j;
                    float v = acc[i][j] * SCALE;
                    split_store(&g_Ph[b][ri][cj], &g_Pl[b][ri][cj], v);
                }
                if ((cta & 3) == 0 && tx == 0) g_d[b][ri] = dacc[i] * SCALE;
            }
        }
    }
}

// ================= out = Ph Xh + Ph Xl + Pl Xh (+d) =================
#define OB_STRIDE 272
#define OU_AH 0
#define OU_AL 10240
#define OU_BH 20480
#define OU_BL (20480 + 32 * OB_STRIDE)
#define OU_BUF (20480 + 2 * 32 * OB_STRIDE)   // 37888
#define OU_SMEM (2 * OU_BUF)                  // 75776

__global__ __launch_bounds__(256) void out_mma_kernel(float* __restrict__ out) {
    extern __shared__ char smem[];
    uint32_t sb = smem_u32(smem);
    int t = threadIdx.x, lane = t & 31, wid = t >> 5;
    int pt = blockIdx.x, mt = blockIdx.y, b = blockIdx.z;
    int wm = (wid >> 2) * 64, wn = (wid & 3) * 32;
    const __nv_bfloat16* Ah = &g_Ph[b][mt * 128][0];
    const __nv_bfloat16* Al = &g_Pl[b][mt * 128][0];
    const __nv_bfloat16* Bh = &g_xh[b][0][pt * 128];
    const __nv_bfloat16* Bl = &g_xl[b][0][pt * 128];

    float acc[4][4][4] = {};

    auto stage = [&](int buf, int kk) {
        uint32_t base = sb + buf * OU_BUF;
#pragma unroll
        for (int i = t; i < 512; i += 256) {
            int r = i >> 2, c = i & 3;
            CPA16(base + OU_AH + r * 80 + c * 16, (const char*)(Ah + (long)r * CCH + kk + c * 8));
            CPA16(base + OU_AL + r * 80 + c * 16, (const char*)(Al + (long)r * CCH + kk + c * 8));
        }
#pragma unroll
        for (int i = t; i < 512; i += 256) {
            int r = i >> 4, c = i & 15;
            CPA16(base + OU_BH + r * OB_STRIDE + c * 16, (const char*)(Bh + (long)(kk + r) * HWN + c * 8));
            CPA16(base + OU_BL + r * OB_STRIDE + c * 16, (const char*)(Bl + (long)(kk + r) * HWN + c * 8));
        }
    };

    stage(0, 0);
    CPA_COMMIT();
    const int S = 8;
    for (int s = 0; s < S; s++) {
        if (s + 1 < S) { stage((s + 1) & 1, (s + 1) * 32); CPA_COMMIT(); CPA_WAIT1(); }
        else CPA_WAIT0();
        __syncthreads();
        uint32_t base = sb + (s & 1) * OU_BUF;
#pragma unroll
        for (int ks = 0; ks < 32; ks += 16) {
            uint32_t afh[4][4], afl[4][4], bfh[4][2], bfl[4][2];
#pragma unroll
            for (int i = 0; i < 4; i++) {
                uint32_t ao = (wm + i * 16 + (lane & 15)) * 80 + ks * 2 + (lane >> 4) * 16;
                ldsm4(afh[i], base + OU_AH + ao);
                ldsm4(afl[i], base + OU_AL + ao);
            }
#pragma unroll
            for (int j = 0; j < 2; j++) {
                uint32_t bo = (ks + (lane & 15)) * OB_STRIDE + (wn + j * 16 + (lane >> 4) * 8) * 2;
                uint32_t r[4];
                ldsm4t(r, base + OU_BH + bo);
                bfh[2 * j][0] = r[0]; bfh[2 * j][1] = r[1];
                bfh[2 * j + 1][0] = r[2]; bfh[2 * j + 1][1] = r[3];
                ldsm4t(r, base + OU_BL + bo);
                bfl[2 * j][0] = r[0]; bfl[2 * j][1] = r[1];
                bfl[2 * j + 1][0] = r[2]; bfl[2 * j + 1][1] = r[3];
            }
#pragma unroll
            for (int i = 0; i < 4; i++)
#pragma unroll
                for (int j = 0; j < 4; j++) {
                    mma_bf16(acc[i][j], afh[i], bfh[j]);
                    mma_bf16(acc[i][j], afh[i], bfl[j]);
                    mma_bf16(acc[i][j], afl[i], bfh[j]);
                }
        }
        __syncthreads();
    }

#pragma unroll
    for (int i = 0; i < 4; i++) {
        int m = mt * 128 + wm + i * 16 + (lane >> 2);
        float d0 = g_d[b][m], d1 = g_d[b][m + 8];
        float* O0 = out + ((long)(b * CCH + m)) * HWN + pt * 128;
        float* O1 = O0 + 8L * HWN;
#pragma unroll
        for (int j = 0; j < 4; j++) {
            int n = wn + j * 8 + (lane & 3) * 2;
            *(float2*)(O0 + n) = make_float2(acc[i][j][0] + d0, acc[i][j][1] + d0);
            *(float2*)(O1 + n) = make_float2(acc[i][j][2] + d1, acc[i][j][3] + d1);
        }
    }
}

// ================= launch =================
extern "C" void kernel_launch(void* const* d_in, const int* in_sizes, int n_in,
                              void* d_out, int out_size) {
    const float* x = (const float*)d_in[0];

    static bool attr_done = false;
    if (!attr_done) {
        cudaFuncSetAttribute(mega_kernel,    cudaFuncAttributeMaxDynamicSharedMemorySize, GR_SMEM);
        cudaFuncSetAttribute(out_mma_kernel, cudaFuncAttributeMaxDynamicSharedMemorySize, OU_SMEM);
        attr_done = true;
    }

    mega_kernel<<<NCTA, 512, GR_SMEM>>>(
        x,
        (const float*)d_in[1], (const float*)d_in[2], (const float*)d_in[3], (const float*)d_in[4],
        (const float*)d_in[5], (const float*)d_in[6], (const float*)d_in[7], (const float*)d_in[8],
        (const float*)d_in[9], (const float*)d_in[10], (const float*)d_in[11], (const float*)d_in[12]);
    out_mma_kernel<<<dim3(32, 2, BATCH), 256, OU_SMEM>>>((float*)d_out);
}

// round 11
// speedup vs baseline: 1.2013x; 1.1376x over previous
#include <cuda_runtime.h>
#include <cuda_fp16.h>
#include <cstdint>

// PatchAttentionLayer on GB300 (sm_103 baseline PTX path).
// BN folded into affine maps; attention via associativity (no NxN map).
// R11: fp16 hi/lo mma (10-bit mantissa) instead of bf16; out GEMM reduced
// from 3 products to 2 (drop Pl*Xh, ~2.4e-4 rel err, under 1e-3 threshold);
// proj rewritten for Cov L2 reuse. R5 launch structure (9 launches) kept —
// mega-kernel fusion measured slower.

#define CCH 256
#define BATCH 8
#define HWN 4096
#define EPS_BN 1e-5f
#define INV_NPOS (1.0f / 32768.0f)
#define SCALE 0.125f

// ================= device scratch =================
__device__ __half g_xh[BATCH][CCH][HWN];   // fp16 hi split, [c][p]
__device__ __half g_xl[BATCH][CCH][HWN];   // fp16 lo split, [c][p]
__device__ float g_S1p[4][BATCH][CCH][CCH];
__device__ float g_S2p[4][BATCH][CCH][CCH];
__device__ float g_s[BATCH][CCH];
__device__ float g_mean[CCH];
__device__ float g_Cov[CCH][CCH];
__device__ float g_A[3][CCH][CCH];
__device__ float g_cvec[3][CCH];
__device__ float g_G[BATCH][CCH][CCH];
__device__ float g_T1[BATCH][CCH][CCH];
__device__ float g_M[BATCH][CCH][CCH];
__device__ float g_d[BATCH][CCH];
__device__ __half g_Ph[BATCH][CCH][CCH];   // fp16 P (no lo split needed)

// ================= mma helpers (sm_80+ baseline PTX) =================
__device__ __forceinline__ uint32_t smem_u32(const void* p) {
    uint32_t a;
    asm("{ .reg .u64 t; cvta.to.shared.u64 t, %1; cvt.u32.u64 %0, t; }" : "=r"(a) : "l"(p));
    return a;
}
__device__ __forceinline__ void ldsm4(uint32_t* r, uint32_t a) {
    asm volatile("ldmatrix.sync.aligned.m8n8.x4.shared.b16 {%0,%1,%2,%3}, [%4];"
                 : "=r"(r[0]), "=r"(r[1]), "=r"(r[2]), "=r"(r[3]) : "r"(a));
}
__device__ __forceinline__ void ldsm4t(uint32_t* r, uint32_t a) {
    asm volatile("ldmatrix.sync.aligned.m8n8.x4.trans.shared.b16 {%0,%1,%2,%3}, [%4];"
                 : "=r"(r[0]), "=r"(r[1]), "=r"(r[2]), "=r"(r[3]) : "r"(a));
}
__device__ __forceinline__ void mma_f16(float* c, const uint32_t* a, const uint32_t* b) {
    asm volatile(
        "mma.sync.aligned.m16n8k16.row.col.f32.f16.f16.f32 "
        "{%0,%1,%2,%3},{%4,%5,%6,%7},{%8,%9},{%0,%1,%2,%3};"
        : "+f"(c[0]), "+f"(c[1]), "+f"(c[2]), "+f"(c[3])
        : "r"(a[0]), "r"(a[1]), "r"(a[2]), "r"(a[3]), "r"(b[0]), "r"(b[1]));
}
#define CPA16(dst, src) asm volatile("cp.async.cg.shared.global [%0], [%1], 16;" :: "r"(dst), "l"(src))
#define CPA_COMMIT()    asm volatile("cp.async.commit_group;")
#define CPA_WAIT1()     asm volatile("cp.async.wait_group 1;")
#define CPA_WAIT0()     asm volatile("cp.async.wait_group 0;")

// ================= prep: fp32 -> hi/lo fp16 + per-(b,c) sums =================
__global__ __launch_bounds__(256) void prep_kernel(const float* __restrict__ x) {
    int c = blockIdx.x, b = blockIdx.y;
    const float4* src = (const float4*)(x + ((long)(b * CCH + c)) * HWN);
    __half2* dh = (__half2*)&g_xh[b][c][0];
    __half2* dl = (__half2*)&g_xl[b][c][0];
    float s = 0.f;
    for (int i = threadIdx.x; i < 1024; i += 256) {
        float4 v = src[i];
        s += (v.x + v.y) + (v.z + v.w);
        __half h0 = __float2half_rn(v.x), h1 = __float2half_rn(v.y);
        __half h2 = __float2half_rn(v.z), h3 = __float2half_rn(v.w);
        __half l0 = __float2half_rn(v.x - __half2float(h0));
        __half l1 = __float2half_rn(v.y - __half2float(h1));
        __half l2 = __float2half_rn(v.z - __half2float(h2));
        __half l3 = __float2half_rn(v.w - __half2float(h3));
        dh[2 * i]     = __halves2half2(h0, h1);
        dh[2 * i + 1] = __halves2half2(h2, h3);
        dl[2 * i]     = __halves2half2(l0, l1);
        dl[2 * i + 1] = __halves2half2(l2, l3);
    }
    __shared__ float sh[256];
    sh[threadIdx.x] = s;
    __syncthreads();
    for (int off = 128; off > 0; off >>= 1) {
        if (threadIdx.x < off) sh[threadIdx.x] += sh[threadIdx.x + off];
        __syncthreads();
    }
    if (threadIdx.x == 0) g_s[b][c] = sh[0];
}

// ================= gram: S1 = H H^T and S2 = H L^T fused (fp16 mma) ==========
#define GR_TILE 10240
#define GR_BUF  (3 * GR_TILE)
#define GR_SMEM (2 * GR_BUF)

__global__ __launch_bounds__(512) void gram_mma_kernel() {
    extern __shared__ char smem[];
    uint32_t sb = smem_u32(smem);
    int t = threadIdx.x, lane = t & 31, wid = t >> 5;
    int split = blockIdx.x, b = blockIdx.z;
    int mt = blockIdx.y >> 1, nt = blockIdx.y & 1;
    const __half* Ag  = &g_xh[b][mt * 128][0];
    const __half* BgH = &g_xh[b][nt * 128][0];
    const __half* BgL = &g_xl[b][nt * 128][0];
    int k0 = split * 1024;
    int grp = wid >> 3, w8 = wid & 7;
    int wm = (w8 >> 2) * 64, wn = (w8 & 3) * 32;

    float acc[4][4][4] = {};

    auto stage = [&](int buf, int kk) {
        uint32_t base = sb + buf * GR_BUF;
        int r = t >> 2, c = t & 3;
        long go = (long)r * HWN + kk + c * 8;
        uint32_t so = r * 80 + c * 16;
        CPA16(base + so,               (const char*)(Ag + go));
        CPA16(base + GR_TILE + so,     (const char*)(BgH + go));
        CPA16(base + 2 * GR_TILE + so, (const char*)(BgL + go));
    };

    stage(0, k0);
    CPA_COMMIT();
    const int S = 32;
    for (int s = 0; s < S; s++) {
        if (s + 1 < S) { stage((s + 1) & 1, k0 + (s + 1) * 32); CPA_COMMIT(); CPA_WAIT1(); }
        else CPA_WAIT0();
        __syncthreads();
        uint32_t aBase = sb + (s & 1) * GR_BUF;
        uint32_t bBase = aBase + GR_TILE + grp * GR_TILE;
#pragma unroll
        for (int ks = 0; ks < 32; ks += 16) {
            uint32_t af[4][4], bf[4][2];
#pragma unroll
            for (int i = 0; i < 4; i++)
                ldsm4(af[i], aBase + (wm + i * 16 + (lane & 15)) * 80 + ks * 2 + (lane >> 4) * 16);
#pragma unroll
            for (int j = 0; j < 2; j++) {
                uint32_t r[4];
                ldsm4(r, bBase + (wn + j * 16 + (lane & 15)) * 80 + ks * 2 + (lane >> 4) * 16);
                bf[2 * j][0] = r[0]; bf[2 * j][1] = r[2];
                bf[2 * j + 1][0] = r[1]; bf[2 * j + 1][1] = r[3];
            }
#pragma unroll
            for (int i = 0; i < 4; i++)
#pragma unroll
                for (int j = 0; j < 4; j++) mma_f16(acc[i][j], af[i], bf[j]);
        }
        __syncthreads();
    }

    float* dst = grp ? &g_S2p[split][b][0][0] : &g_S1p[split][b][0][0];
#pragma unroll
    for (int i = 0; i < 4; i++) {
        int m = mt * 128 + wm + i * 16 + (lane >> 2);
#pragma unroll
        for (int j = 0; j < 4; j++) {
            int n = nt * 128 + wn + j * 8 + (lane & 3) * 2;
            *(float2*)(dst + (long)m * CCH + n) = make_float2(acc[i][j][0], acc[i][j][1]);
            *(float2*)(dst + (long)(m + 8) * CCH + n) = make_float2(acc[i][j][2], acc[i][j][3]);
        }
    }
}

// G[b] = sum_s (S1 + S2) + (sum_s S2)^T
__global__ __launch_bounds__(256) void reduceG_kernel() {
    __shared__ float tt[32][33];
    int jt = blockIdx.x * 32, it = blockIdx.y * 32, b = blockIdx.z;
    int lx = threadIdx.x & 31, ly = threadIdx.x >> 5;
    for (int r = ly; r < 32; r += 8) {
        float s = 0.f;
#pragma unroll
        for (int sp = 0; sp < 4; sp++) s += g_S2p[sp][b][jt + r][it + lx];
        tt[r][lx] = s;
    }
    __syncthreads();
    for (int r = ly; r < 32; r += 8) {
        float s = tt[lx][r];
#pragma unroll
        for (int sp = 0; sp < 4; sp++)
            s += g_S1p[sp][b][it + r][jt + lx] + g_S2p[sp][b][it + r][jt + lx];
        g_G[b][it + r][jt + lx] = s;
    }
}

// ================= cov (+mean fused) =================
__global__ void cov_kernel() {
    int c = blockIdx.x, t = threadIdx.x;
    float mt_ = 0.f;
#pragma unroll
    for (int b = 0; b < BATCH; b++) mt_ += g_s[b][t];
    mt_ *= INV_NPOS;
    __shared__ float mc_sh;
    if (t == c) mc_sh = mt_;
    __syncthreads();
    float s = 0.f;
#pragma unroll
    for (int b = 0; b < BATCH; b++) s += g_G[b][c][t];
    g_Cov[c][t] = s * INV_NPOS - mc_sh * mt_;
    if (c == 0) g_mean[t] = mt_;
}

// ================= BN fold: 8 outputs per CTA sharing one Cov pass ==========
__global__ __launch_bounds__(256) void proj_kernel(
    const float* __restrict__ Wq, const float* __restrict__ bq, const float* __restrict__ gq, const float* __restrict__ beq,
    const float* __restrict__ Wk, const float* __restrict__ bk, const float* __restrict__ gk, const float* __restrict__ bek,
    const float* __restrict__ Wv, const float* __restrict__ bv, const float* __restrict__ gv, const float* __restrict__ bev) {
    __shared__ float ws8[8][CCH];
    __shared__ float s1[256], s2[256];
    __shared__ float a_sh, c_sh;
    int t = threadIdx.x;
    int base = blockIdx.x * 8;          // 96 CTAs * 8 = 768 units; 256 % 8 == 0 so tp uniform
    int tp = base >> 8, o0 = base & 255;
    const float *W, *bb, *gg, *be;
    if (tp == 0) { W = Wq; bb = bq; gg = gq; be = beq; }
    else if (tp == 1) { W = Wk; bb = bk; gg = gk; be = bek; }
    else { W = Wv; bb = bv; gg = gv; be = bev; }
#pragma unroll
    for (int r = 0; r < 8; r++) ws8[r][t] = W[(o0 + r) * CCH + t];
    __syncthreads();
    float mt_ = g_mean[t];
    float col[8] = {};
    for (int c = 0; c < CCH; c++) {
        float cv = g_Cov[c][t];
#pragma unroll
        for (int r = 0; r < 8; r++) col[r] += ws8[r][c] * cv;
    }
#pragma unroll
    for (int r = 0; r < 8; r++) {
        float w = ws8[r][t];
        s1[t] = col[r] * w;
        s2[t] = w * mt_;
        __syncthreads();
        for (int off = 128; off > 0; off >>= 1) {
            if (t < off) { s1[t] += s1[t + off]; s2[t] += s2[t + off]; }
            __syncthreads();
        }
        if (t == 0) {
            int o = o0 + r;
            float var = s1[0];
            float mu = s2[0] + bb[o];
            float a = gg[o] * rsqrtf(var + EPS_BN);
            a_sh = a;
            c_sh = (bb[o] - mu) * a + be[o];
        }
        __syncthreads();
        g_A[tp][o0 + r][t] = a_sh * w;
        if (t == 0) g_cvec[tp][o0 + r] = c_sh;
        __syncthreads();
    }
}

// ================= fp32 glue GEMM micro-kernel =================
__device__ __forceinline__ void mma16f(const float (*As)[65], const float (*Bs)[65],
                                       int ty, int tx, float acc[4][4]) {
#pragma unroll
    for (int kk = 0; kk < 16; kk++) {
        float a[4], b[4];
#pragma unroll
        for (int i = 0; i < 4; i++) a[i] = As[kk][ty * 4 + i];
#pragma unroll
        for (int j = 0; j < 4; j++) b[j] = Bs[kk][tx * 4 + j];
#pragma unroll
        for (int i = 0; i < 4; i++)
#pragma unroll
            for (int j = 0; j < 4; j++) acc[i][j] += a[i] * b[j];
    }
}

// T1_b = G_b * Ak^T (NT)
__global__ void t1_kernel() {
    int b = blockIdx.z;
    int rowBase = blockIdx.y * 64, colBase = blockIdx.x * 64;
    __shared__ float As[16][65], Bs[16][65];
    int t = threadIdx.x, tx = t & 15, ty = t >> 4;
    int r = t >> 2, kseg = (t & 3) * 4;
    float acc[4][4] = {};
    const float* A = &g_G[b][0][0];
    const float* B = &g_A[1][0][0];
    for (int k0 = 0; k0 < CCH; k0 += 16) {
        float4 av = *(const float4*)(A + (rowBase + r) * CCH + k0 + kseg);
        float4 bv = *(const float4*)(B + (colBase + r) * CCH + k0 + kseg);
        As[kseg + 0][r] = av.x; As[kseg + 1][r] = av.y; As[kseg + 2][r] = av.z; As[kseg + 3][r] = av.w;
        Bs[kseg + 0][r] = bv.x; Bs[kseg + 1][r] = bv.y; Bs[kseg + 2][r] = bv.z; Bs[kseg + 3][r] = bv.w;
        __syncthreads();
        mma16f(As, Bs, ty, tx, acc);
        __syncthreads();
    }
#pragma unroll
    for (int i = 0; i < 4; i++)
#pragma unroll
        for (int j = 0; j < 4; j++)
            g_T1[b][rowBase + ty * 4 + i][colBase + tx * 4 + j] = acc[i][j];
}

// M_b = Av * T1_b + rank-1 corrections (uw fused in prologue)
__global__ void m_kernel() {
    int b = blockIdx.z;
    int rowBase = blockIdx.y * 64, colBase = blockIdx.x * 64;
    __shared__ float As[16][65], Bs[16][65];
    __shared__ float ss[CCH], su[64], sw[64];
    int t = threadIdx.x, tx = t & 15, ty = t >> 4;
    int ar = t >> 2, akseg = (t & 3) * 4;
    int bkk = t >> 4, bcc = (t & 15) * 4;
    ss[t] = g_s[b][t];
    __syncthreads();
    if (t < 64) {
        float a = 0.f;
        const float* row = &g_A[2][rowBase + t][0];
        for (int c = 0; c < CCH; c++) a += row[c] * ss[c];
        su[t] = a;
    } else if (t < 128) {
        int j = t - 64;
        float a = 0.f;
        const float* row = &g_A[1][colBase + j][0];
        for (int c = 0; c < CCH; c++) a += row[c] * ss[c];
        sw[j] = a;
    }
    float acc[4][4] = {};
    const float* A = &g_A[2][0][0];
    const float* B = &g_T1[b][0][0];
    for (int k0 = 0; k0 < CCH; k0 += 16) {
        float4 av = *(const float4*)(A + (rowBase + ar) * CCH + k0 + akseg);
        float4 bv = *(const float4*)(B + (k0 + bkk) * CCH + colBase + bcc);
        As[akseg + 0][ar] = av.x; As[akseg + 1][ar] = av.y; As[akseg + 2][ar] = av.z; As[akseg + 3][ar] = av.w;
        Bs[bkk][bcc + 0] = bv.x; Bs[bkk][bcc + 1] = bv.y; Bs[bkk][bcc + 2] = bv.z; Bs[bkk][bcc + 3] = bv.w;
        __syncthreads();
        mma16f(As, Bs, ty, tx, acc);
        __syncthreads();
    }
#pragma unroll
    for (int i = 0; i < 4; i++) {
        int ri = rowBase + ty * 4 + i;
        float u = su[ty * 4 + i], cv = g_cvec[2][ri];
#pragma unroll
        for (int j = 0; j < 4; j++) {
            int cj = colBase + tx * 4 + j;
            float ck = g_cvec[1][cj];
            g_M[b][ri][cj] = acc[i][j] + u * ck + cv * sw[tx * 4 + j] + 4096.0f * cv * ck;
        }
    }
}

// P_b = scale * M_b * Aq -> fp16 (hi only); d fused (colBase==0 blocks)
__global__ void p_kernel() {
    int b = blockIdx.z;
    int rowBase = blockIdx.y * 64, colBase = blockIdx.x * 64;
    __shared__ float As[16][65], Bs[16][65];
    __shared__ float cqs[CCH];
    int t = threadIdx.x, tx = t & 15, ty = t >> 4;
    int ar = t >> 2, akseg = (t & 3) * 4;
    int bkk = t >> 4, bcc = (t & 15) * 4;
    cqs[t] = g_cvec[0][t];
    float acc[4][4] = {};
    float dacc[4] = {};
    const float* A = &g_M[b][0][0];
    const float* B = &g_A[0][0][0];
    for (int k0 = 0; k0 < CCH; k0 += 16) {
        float4 av = *(const float4*)(A + (rowBase + ar) * CCH + k0 + akseg);
        float4 bv = *(const float4*)(B + (k0 + bkk) * CCH + colBase + bcc);
        As[akseg + 0][ar] = av.x; As[akseg + 1][ar] = av.y; As[akseg + 2][ar] = av.z; As[akseg + 3][ar] = av.w;
        Bs[bkk][bcc + 0] = bv.x; Bs[bkk][bcc + 1] = bv.y; Bs[bkk][bcc + 2] = bv.z; Bs[bkk][bcc + 3] = bv.w;
        __syncthreads();
        mma16f(As, Bs, ty, tx, acc);
        if (tx == 0) {
#pragma unroll
            for (int kk = 0; kk < 16; kk++) {
                float cq = cqs[k0 + kk];
#pragma unroll
                for (int i = 0; i < 4; i++) dacc[i] += As[kk][ty * 4 + i] * cq;
            }
        }
        __syncthreads();
    }
#pragma unroll
    for (int i = 0; i < 4; i++) {
        int ri = rowBase + ty * 4 + i;
#pragma unroll
        for (int j = 0; j < 4; j++) {
            int cj = colBase + tx * 4 + j;
            g_Ph[b][ri][cj] = __float2half_rn(acc[i][j] * SCALE);
        }
        if (blockIdx.x == 0 && tx == 0) g_d[b][ri] = dacc[i] * SCALE;
    }
}

// ================= out = Ph Xh + Ph Xl (+d), fp16 2-product =================
#define OB_STRIDE 272   // bytes per B smem row (128 fp16 + 8 pad)
#define OU_AH 0
#define OU_BH 10240
#define OU_BL (10240 + 32 * OB_STRIDE)
#define OU_BUF (10240 + 2 * 32 * OB_STRIDE)  // 27648
#define OU_SMEM (2 * OU_BUF)                 // 55296

__global__ __launch_bounds__(256) void out_mma_kernel(float* __restrict__ out) {
    extern __shared__ char smem[];
    uint32_t sb = smem_u32(smem);
    int t = threadIdx.x, lane = t & 31, wid = t >> 5;
    int pt = blockIdx.x, mt = blockIdx.y, b = blockIdx.z;
    int wm = (wid >> 2) * 64, wn = (wid & 3) * 32;
    const __half* Ah = &g_Ph[b][mt * 128][0];
    const __half* Bh = &g_xh[b][0][pt * 128];
    const __half* Bl = &g_xl[b][0][pt * 128];

    float acc[4][4][4] = {};

    auto stage = [&](int buf, int kk) {
        uint32_t base = sb + buf * OU_BUF;
#pragma unroll
        for (int i = t; i < 512; i += 256) {   // A tile: 128 rows x 4 chunks
            int r = i >> 2, c = i & 3;
            CPA16(base + OU_AH + r * 80 + c * 16, (const char*)(Ah + (long)r * CCH + kk + c * 8));
        }
#pragma unroll
        for (int i = t; i < 512; i += 256) {   // B tiles: 32 rows (k=c') x 16 chunks (n=p)
            int r = i >> 4, c = i & 15;
            CPA16(base + OU_BH + r * OB_STRIDE + c * 16, (const char*)(Bh + (long)(kk + r) * HWN + c * 8));
            CPA16(base + OU_BL + r * OB_STRIDE + c * 16, (const char*)(Bl + (long)(kk + r) * HWN + c * 8));
        }
    };

    stage(0, 0);
    CPA_COMMIT();
    const int S = 8;  // K=256 / 32
    for (int s = 0; s < S; s++) {
        if (s + 1 < S) { stage((s + 1) & 1, (s + 1) * 32); CPA_COMMIT(); CPA_WAIT1(); }
        else CPA_WAIT0();
        __syncthreads();
        uint32_t base = sb + (s & 1) * OU_BUF;
#pragma unroll
        for (int ks = 0; ks < 32; ks += 16) {
            uint32_t afh[4][4], bfh[4][2], bfl[4][2];
#pragma unroll
            for (int i = 0; i < 4; i++) {
                uint32_t ao = (wm + i * 16 + (lane & 15)) * 80 + ks * 2 + (lane >> 4) * 16;
                ldsm4(afh[i], base + OU_AH + ao);
            }
#pragma unroll
            for (int j = 0; j < 2; j++) {
                uint32_t bo = (ks + (lane & 15)) * OB_STRIDE + (wn + j * 16 + (lane >> 4) * 8) * 2;
                uint32_t r[4];
                ldsm4t(r, base + OU_BH + bo);
                bfh[2 * j][0] = r[0]; bfh[2 * j][1] = r[1];
                bfh[2 * j + 1][0] = r[2]; bfh[2 * j + 1][1] = r[3];
                ldsm4t(r, base + OU_BL + bo);
                bfl[2 * j][0] = r[0]; bfl[2 * j][1] = r[1];
                bfl[2 * j + 1][0] = r[2]; bfl[2 * j + 1][1] = r[3];
            }
#pragma unroll
            for (int i = 0; i < 4; i++)
#pragma unroll
                for (int j = 0; j < 4; j++) {
                    mma_f16(acc[i][j], afh[i], bfh[j]);
                    mma_f16(acc[i][j], afh[i], bfl[j]);
                }
        }
        __syncthreads();
    }

#pragma unroll
    for (int i = 0; i < 4; i++) {
        int m = mt * 128 + wm + i * 16 + (lane >> 2);
        float d0 = g_d[b][m], d1 = g_d[b][m + 8];
        float* O0 = out + ((long)(b * CCH + m)) * HWN + pt * 128;
        float* O1 = O0 + 8L * HWN;
#pragma unroll
        for (int j = 0; j < 4; j++) {
            int n = wn + j * 8 + (lane & 3) * 2;
            *(float2*)(O0 + n) = make_float2(acc[i][j][0] + d0, acc[i][j][1] + d0);
            *(float2*)(O1 + n) = make_float2(acc[i][j][2] + d1, acc[i][j][3] + d1);
        }
    }
}

// ================= launch =================
extern "C" void kernel_launch(void* const* d_in, const int* in_sizes, int n_in,
                              void* d_out, int out_size) {
    const float* x = (const float*)d_in[0];

    static bool attr_done = false;
    if (!attr_done) {
        cudaFuncSetAttribute(gram_mma_kernel, cudaFuncAttributeMaxDynamicSharedMemorySize, GR_SMEM);
        cudaFuncSetAttribute(out_mma_kernel,  cudaFuncAttributeMaxDynamicSharedMemorySize, OU_SMEM);
        attr_done = true;
    }

    prep_kernel<<<dim3(CCH, BATCH), 256>>>(x);
    gram_mma_kernel<<<dim3(4, 4, BATCH), 512, GR_SMEM>>>();
    reduceG_kernel<<<dim3(8, 8, BATCH), 256>>>();
    cov_kernel<<<CCH, 256>>>();
    proj_kernel<<<96, 256>>>(
        (const float*)d_in[1], (const float*)d_in[2], (const float*)d_in[3], (const float*)d_in[4],
        (const float*)d_in[5], (const float*)d_in[6], (const float*)d_in[7], (const float*)d_in[8],
        (const float*)d_in[9], (const float*)d_in[10], (const float*)d_in[11], (const float*)d_in[12]);
    t1_kernel<<<dim3(4, 4, BATCH), 256>>>();
    m_kernel<<<dim3(4, 4, BATCH), 256>>>();
    p_kernel<<<dim3(4, 4, BATCH), 256>>>();
    out_mma_kernel<<<dim3(32, 2, BATCH), 256, OU_SMEM>>>((float*)d_out);
}

// round 12
// speedup vs baseline: 1.3631x; 1.1347x over previous
#include <cuda_runtime.h>
#include <cuda_fp16.h>
#include <cstdint>

// PatchAttentionLayer on GB300 (sm_103 baseline PTX path).
// BN folded into affine maps; attention via associativity (no NxN map).
// R12: calibrated-error-budget version. Plain fp16 mma for gram (H H^T) and
// out (Ph Xh) — lo-split products dropped (~2e-4 each, quadrature ~4.5e-4,
// under 1e-3). xl eliminated entirely. cov fused into reduceG. 8 launches.

#define CCH 256
#define BATCH 8
#define HWN 4096
#define EPS_BN 1e-5f
#define INV_NPOS (1.0f / 32768.0f)
#define SCALE 0.125f

// ================= device scratch =================
__device__ __half g_xh[BATCH][CCH][HWN];   // fp16 x, [c][p]
__device__ float g_S1p[4][BATCH][CCH][CCH];
__device__ float g_s[BATCH][CCH];
__device__ float g_mean[CCH];
__device__ float g_Cov[CCH][CCH];
__device__ float g_A[3][CCH][CCH];
__device__ float g_cvec[3][CCH];
__device__ float g_G[BATCH][CCH][CCH];
__device__ float g_T1[BATCH][CCH][CCH];
__device__ float g_M[BATCH][CCH][CCH];
__device__ float g_d[BATCH][CCH];
__device__ __half g_Ph[BATCH][CCH][CCH];

// ================= mma helpers (sm_80+ baseline PTX) =================
__device__ __forceinline__ uint32_t smem_u32(const void* p) {
    uint32_t a;
    asm("{ .reg .u64 t; cvta.to.shared.u64 t, %1; cvt.u32.u64 %0, t; }" : "=r"(a) : "l"(p));
    return a;
}
__device__ __forceinline__ void ldsm4(uint32_t* r, uint32_t a) {
    asm volatile("ldmatrix.sync.aligned.m8n8.x4.shared.b16 {%0,%1,%2,%3}, [%4];"
                 : "=r"(r[0]), "=r"(r[1]), "=r"(r[2]), "=r"(r[3]) : "r"(a));
}
__device__ __forceinline__ void ldsm4t(uint32_t* r, uint32_t a) {
    asm volatile("ldmatrix.sync.aligned.m8n8.x4.trans.shared.b16 {%0,%1,%2,%3}, [%4];"
                 : "=r"(r[0]), "=r"(r[1]), "=r"(r[2]), "=r"(r[3]) : "r"(a));
}
__device__ __forceinline__ void mma_f16(float* c, const uint32_t* a, const uint32_t* b) {
    asm volatile(
        "mma.sync.aligned.m16n8k16.row.col.f32.f16.f16.f32 "
        "{%0,%1,%2,%3},{%4,%5,%6,%7},{%8,%9},{%0,%1,%2,%3};"
        : "+f"(c[0]), "+f"(c[1]), "+f"(c[2]), "+f"(c[3])
        : "r"(a[0]), "r"(a[1]), "r"(a[2]), "r"(a[3]), "r"(b[0]), "r"(b[1]));
}
#define CPA16(dst, src) asm volatile("cp.async.cg.shared.global [%0], [%1], 16;" :: "r"(dst), "l"(src))
#define CPA_COMMIT()    asm volatile("cp.async.commit_group;")
#define CPA_WAIT1()     asm volatile("cp.async.wait_group 1;")
#define CPA_WAIT0()     asm volatile("cp.async.wait_group 0;")

// ================= prep: fp32 -> fp16 + per-(b,c) sums =================
__global__ __launch_bounds__(256) void prep_kernel(const float* __restrict__ x) {
    int c = blockIdx.x, b = blockIdx.y;
    const float4* src = (const float4*)(x + ((long)(b * CCH + c)) * HWN);
    __half2* dh = (__half2*)&g_xh[b][c][0];
    float s = 0.f;
    for (int i = threadIdx.x; i < 1024; i += 256) {
        float4 v = src[i];
        s += (v.x + v.y) + (v.z + v.w);
        dh[2 * i]     = __halves2half2(__float2half_rn(v.x), __float2half_rn(v.y));
        dh[2 * i + 1] = __halves2half2(__float2half_rn(v.z), __float2half_rn(v.w));
    }
    __shared__ float sh[256];
    sh[threadIdx.x] = s;
    __syncthreads();
    for (int off = 128; off > 0; off >>= 1) {
        if (threadIdx.x < off) sh[threadIdx.x] += sh[threadIdx.x + off];
        __syncthreads();
    }
    if (threadIdx.x == 0) g_s[b][c] = sh[0];
}

// ================= gram: S1 = H H^T (fp16 mma, split-K x4) =================
#define GR_TILE 10240                 // 128 rows * 80 B (32 fp16 + pad)
#define GR_BUF  (2 * GR_TILE)         // A, B
#define GR_SMEM (2 * GR_BUF)          // double buffered: 40960

__global__ __launch_bounds__(256) void gram_mma_kernel() {
    extern __shared__ char smem[];
    uint32_t sb = smem_u32(smem);
    int t = threadIdx.x, lane = t & 31, wid = t >> 5;
    int split = blockIdx.x, b = blockIdx.z;
    int mt = blockIdx.y >> 1, nt = blockIdx.y & 1;
    const __half* Ag = &g_xh[b][mt * 128][0];
    const __half* Bg = &g_xh[b][nt * 128][0];
    int k0 = split * 1024;
    int wm = (wid >> 2) * 64, wn = (wid & 3) * 32;

    float acc[4][4][4] = {};

    auto stage = [&](int buf, int kk) {
        uint32_t base = sb + buf * GR_BUF;
#pragma unroll
        for (int i = t; i < 512; i += 256) {
            int r = i >> 2, c = i & 3;
            long go = (long)r * HWN + kk + c * 8;
            uint32_t so = r * 80 + c * 16;
            CPA16(base + so,           (const char*)(Ag + go));
            CPA16(base + GR_TILE + so, (const char*)(Bg + go));
        }
    };

    stage(0, k0);
    CPA_COMMIT();
    const int S = 32;
    for (int s = 0; s < S; s++) {
        if (s + 1 < S) { stage((s + 1) & 1, k0 + (s + 1) * 32); CPA_COMMIT(); CPA_WAIT1(); }
        else CPA_WAIT0();
        __syncthreads();
        uint32_t aBase = sb + (s & 1) * GR_BUF;
        uint32_t bBase = aBase + GR_TILE;
#pragma unroll
        for (int ks = 0; ks < 32; ks += 16) {
            uint32_t af[4][4], bf[4][2];
#pragma unroll
            for (int i = 0; i < 4; i++)
                ldsm4(af[i], aBase + (wm + i * 16 + (lane & 15)) * 80 + ks * 2 + (lane >> 4) * 16);
#pragma unroll
            for (int j = 0; j < 2; j++) {
                uint32_t r[4];
                ldsm4(r, bBase + (wn + j * 16 + (lane & 15)) * 80 + ks * 2 + (lane >> 4) * 16);
                bf[2 * j][0] = r[0]; bf[2 * j][1] = r[2];
                bf[2 * j + 1][0] = r[1]; bf[2 * j + 1][1] = r[3];
            }
#pragma unroll
            for (int i = 0; i < 4; i++)
#pragma unroll
                for (int j = 0; j < 4; j++) mma_f16(acc[i][j], af[i], bf[j]);
        }
        __syncthreads();
    }

    float* dst = &g_S1p[split][b][0][0];
#pragma unroll
    for (int i = 0; i < 4; i++) {
        int m = mt * 128 + wm + i * 16 + (lane >> 2);
#pragma unroll
        for (int j = 0; j < 4; j++) {
            int n = nt * 128 + wn + j * 8 + (lane & 3) * 2;
            *(float2*)(dst + (long)m * CCH + n) = make_float2(acc[i][j][0], acc[i][j][1]);
            *(float2*)(dst + (long)(m + 8) * CCH + n) = make_float2(acc[i][j][2], acc[i][j][3]);
        }
    }
}

// ================= reduceG + cov + mean fused =================
// G[b] = sum_sp S1p (H H^T is symmetric; all tiles computed directly).
// Cov = (sum_b G)/N - m m^T. Block (0,0) also writes g_mean.
__global__ __launch_bounds__(256) void reduceG_cov_kernel() {
    int jt = blockIdx.x * 32, it = blockIdx.y * 32;
    int lx = threadIdx.x & 31, ly = threadIdx.x >> 5;
    float mc = 0.f;
#pragma unroll
    for (int b = 0; b < BATCH; b++) mc += g_s[b][jt + lx];
    mc *= INV_NPOS;
    float gsum[4] = {};
    for (int b = 0; b < BATCH; b++) {
#pragma unroll
        for (int q = 0; q < 4; q++) {
            int r = ly + q * 8;
            float s = 0.f;
#pragma unroll
            for (int sp = 0; sp < 4; sp++) s += g_S1p[sp][b][it + r][jt + lx];
            g_G[b][it + r][jt + lx] = s;
            gsum[q] += s;
        }
    }
#pragma unroll
    for (int q = 0; q < 4; q++) {
        int r = ly + q * 8;
        float mr = 0.f;
#pragma unroll
        for (int b = 0; b < BATCH; b++) mr += g_s[b][it + r];
        mr *= INV_NPOS;
        g_Cov[it + r][jt + lx] = gsum[q] * INV_NPOS - mr * mc;
    }
    if (blockIdx.x == 0 && blockIdx.y == 0) {
        int t = threadIdx.x;
        float m = 0.f;
#pragma unroll
        for (int b = 0; b < BATCH; b++) m += g_s[b][t];
        g_mean[t] = m * INV_NPOS;
    }
}

// ================= BN fold: 8 outputs per CTA sharing one Cov pass ==========
__global__ __launch_bounds__(256) void proj_kernel(
    const float* __restrict__ Wq, const float* __restrict__ bq, const float* __restrict__ gq, const float* __restrict__ beq,
    const float* __restrict__ Wk, const float* __restrict__ bk, const float* __restrict__ gk, const float* __restrict__ bek,
    const float* __restrict__ Wv, const float* __restrict__ bv, const float* __restrict__ gv, const float* __restrict__ bev) {
    __shared__ float ws8[8][CCH];
    __shared__ float s1[256], s2[256];
    __shared__ float a_sh, c_sh;
    int t = threadIdx.x;
    int base = blockIdx.x * 8;
    int tp = base >> 8, o0 = base & 255;
    const float *W, *bb, *gg, *be;
    if (tp == 0) { W = Wq; bb = bq; gg = gq; be = beq; }
    else if (tp == 1) { W = Wk; bb = bk; gg = gk; be = bek; }
    else { W = Wv; bb = bv; gg = gv; be = bev; }
#pragma unroll
    for (int r = 0; r < 8; r++) ws8[r][t] = W[(o0 + r) * CCH + t];
    __syncthreads();
    float mt_ = g_mean[t];
    float col[8] = {};
    for (int c = 0; c < CCH; c++) {
        float cv = g_Cov[c][t];
#pragma unroll
        for (int r = 0; r < 8; r++) col[r] += ws8[r][c] * cv;
    }
#pragma unroll
    for (int r = 0; r < 8; r++) {
        float w = ws8[r][t];
        s1[t] = col[r] * w;
        s2[t] = w * mt_;
        __syncthreads();
        for (int off = 128; off > 0; off >>= 1) {
            if (t < off) { s1[t] += s1[t + off]; s2[t] += s2[t + off]; }
            __syncthreads();
        }
        if (t == 0) {
            int o = o0 + r;
            float var = s1[0];
            float mu = s2[0] + bb[o];
            float a = gg[o] * rsqrtf(var + EPS_BN);
            a_sh = a;
            c_sh = (bb[o] - mu) * a + be[o];
        }
        __syncthreads();
        g_A[tp][o0 + r][t] = a_sh * w;
        if (t == 0) g_cvec[tp][o0 + r] = c_sh;
        __syncthreads();
    }
}

// ================= fp32 glue GEMM micro-kernel =================
__device__ __forceinline__ void mma16f(const float (*As)[65], const float (*Bs)[65],
                                       int ty, int tx, float acc[4][4]) {
#pragma unroll
    for (int kk = 0; kk < 16; kk++) {
        float a[4], b[4];
#pragma unroll
        for (int i = 0; i < 4; i++) a[i] = As[kk][ty * 4 + i];
#pragma unroll
        for (int j = 0; j < 4; j++) b[j] = Bs[kk][tx * 4 + j];
#pragma unroll
        for (int i = 0; i < 4; i++)
#pragma unroll
            for (int j = 0; j < 4; j++) acc[i][j] += a[i] * b[j];
    }
}

// T1_b = G_b * Ak^T (NT)
__global__ void t1_kernel() {
    int b = blockIdx.z;
    int rowBase = blockIdx.y * 64, colBase = blockIdx.x * 64;
    __shared__ float As[16][65], Bs[16][65];
    int t = threadIdx.x, tx = t & 15, ty = t >> 4;
    int r = t >> 2, kseg = (t & 3) * 4;
    float acc[4][4] = {};
    const float* A = &g_G[b][0][0];
    const float* B = &g_A[1][0][0];
    for (int k0 = 0; k0 < CCH; k0 += 16) {
        float4 av = *(const float4*)(A + (rowBase + r) * CCH + k0 + kseg);
        float4 bv = *(const float4*)(B + (colBase + r) * CCH + k0 + kseg);
        As[kseg + 0][r] = av.x; As[kseg + 1][r] = av.y; As[kseg + 2][r] = av.z; As[kseg + 3][r] = av.w;
        Bs[kseg + 0][r] = bv.x; Bs[kseg + 1][r] = bv.y; Bs[kseg + 2][r] = bv.z; Bs[kseg + 3][r] = bv.w;
        __syncthreads();
        mma16f(As, Bs, ty, tx, acc);
        __syncthreads();
    }
#pragma unroll
    for (int i = 0; i < 4; i++)
#pragma unroll
        for (int j = 0; j < 4; j++)
            g_T1[b][rowBase + ty * 4 + i][colBase + tx * 4 + j] = acc[i][j];
}

// M_b = Av * T1_b + rank-1 corrections (uw fused in prologue)
__global__ void m_kernel() {
    int b = blockIdx.z;
    int rowBase = blockIdx.y * 64, colBase = blockIdx.x * 64;
    __shared__ float As[16][65], Bs[16][65];
    __shared__ float ss[CCH], su[64], sw[64];
    int t = threadIdx.x, tx = t & 15, ty = t >> 4;
    int ar = t >> 2, akseg = (t & 3) * 4;
    int bkk = t >> 4, bcc = (t & 15) * 4;
    ss[t] = g_s[b][t];
    __syncthreads();
    if (t < 64) {
        float a = 0.f;
        const float* row = &g_A[2][rowBase + t][0];
        for (int c = 0; c < CCH; c++) a += row[c] * ss[c];
        su[t] = a;
    } else if (t < 128) {
        int j = t - 64;
        float a = 0.f;
        const float* row = &g_A[1][colBase + j][0];
        for (int c = 0; c < CCH; c++) a += row[c] * ss[c];
        sw[j] = a;
    }
    float acc[4][4] = {};
    const float* A = &g_A[2][0][0];
    const float* B = &g_T1[b][0][0];
    for (int k0 = 0; k0 < CCH; k0 += 16) {
        float4 av = *(const float4*)(A + (rowBase + ar) * CCH + k0 + akseg);
        float4 bv = *(const float4*)(B + (k0 + bkk) * CCH + colBase + bcc);
        As[akseg + 0][ar] = av.x; As[akseg + 1][ar] = av.y; As[akseg + 2][ar] = av.z; As[akseg + 3][ar] = av.w;
        Bs[bkk][bcc + 0] = bv.x; Bs[bkk][bcc + 1] = bv.y; Bs[bkk][bcc + 2] = bv.z; Bs[bkk][bcc + 3] = bv.w;
        __syncthreads();
        mma16f(As, Bs, ty, tx, acc);
        __syncthreads();
    }
#pragma unroll
    for (int i = 0; i < 4; i++) {
        int ri = rowBase + ty * 4 + i;
        float u = su[ty * 4 + i], cv = g_cvec[2][ri];
#pragma unroll
        for (int j = 0; j < 4; j++) {
            int cj = colBase + tx * 4 + j;
            float ck = g_cvec[1][cj];
            g_M[b][ri][cj] = acc[i][j] + u * ck + cv * sw[tx * 4 + j] + 4096.0f * cv * ck;
        }
    }
}

// P_b = scale * M_b * Aq -> fp16; d fused (colBase==0 blocks)
__global__ void p_kernel() {
    int b = blockIdx.z;
    int rowBase = blockIdx.y * 64, colBase = blockIdx.x * 64;
    __shared__ float As[16][65], Bs[16][65];
    __shared__ float cqs[CCH];
    int t = threadIdx.x, tx = t & 15, ty = t >> 4;
    int ar = t >> 2, akseg = (t & 3) * 4;
    int bkk = t >> 4, bcc = (t & 15) * 4;
    cqs[t] = g_cvec[0][t];
    float acc[4][4] = {};
    float dacc[4] = {};
    const float* A = &g_M[b][0][0];
    const float* B = &g_A[0][0][0];
    for (int k0 = 0; k0 < CCH; k0 += 16) {
        float4 av = *(const float4*)(A + (rowBase + ar) * CCH + k0 + akseg);
        float4 bv = *(const float4*)(B + (k0 + bkk) * CCH + colBase + bcc);
        As[akseg + 0][ar] = av.x; As[akseg + 1][ar] = av.y; As[akseg + 2][ar] = av.z; As[akseg + 3][ar] = av.w;
        Bs[bkk][bcc + 0] = bv.x; Bs[bkk][bcc + 1] = bv.y; Bs[bkk][bcc + 2] = bv.z; Bs[bkk][bcc + 3] = bv.w;
        __syncthreads();
        mma16f(As, Bs, ty, tx, acc);
        if (tx == 0) {
#pragma unroll
            for (int kk = 0; kk < 16; kk++) {
                float cq = cqs[k0 + kk];
#pragma unroll
                for (int i = 0; i < 4; i++) dacc[i] += As[kk][ty * 4 + i] * cq;
            }
        }
        __syncthreads();
    }
#pragma unroll
    for (int i = 0; i < 4; i++) {
        int ri = rowBase + ty * 4 + i;
#pragma unroll
        for (int j = 0; j < 4; j++) {
            int cj = colBase + tx * 4 + j;
            g_Ph[b][ri][cj] = __float2half_rn(acc[i][j] * SCALE);
        }
        if (blockIdx.x == 0 && tx == 0) g_d[b][ri] = dacc[i] * SCALE;
    }
}

// ================= out = Ph Xh (+d), fp16 single product =================
#define OB_STRIDE 272   // bytes per B smem row (128 fp16 + 8 pad)
#define OU_AH 0
#define OU_BH 10240
#define OU_BUF (10240 + 32 * OB_STRIDE)      // 18944
#define OU_SMEM (2 * OU_BUF)                 // 37888

__global__ __launch_bounds__(256) void out_mma_kernel(float* __restrict__ out) {
    extern __shared__ char smem[];
    uint32_t sb = smem_u32(smem);
    int t = threadIdx.x, lane = t & 31, wid = t >> 5;
    int pt = blockIdx.x, mt = blockIdx.y, b = blockIdx.z;
    int wm = (wid >> 2) * 64, wn = (wid & 3) * 32;
    const __half* Ah = &g_Ph[b][mt * 128][0];
    const __half* Bh = &g_xh[b][0][pt * 128];

    float acc[4][4][4] = {};

    auto stage = [&](int buf, int kk) {
        uint32_t base = sb + buf * OU_BUF;
#pragma unroll
        for (int i = t; i < 512; i += 256) {   // A tile: 128 rows x 4 chunks
            int r = i >> 2, c = i & 3;
            CPA16(base + OU_AH + r * 80 + c * 16, (const char*)(Ah + (long)r * CCH + kk + c * 8));
        }
#pragma unroll
        for (int i = t; i < 512; i += 256) {   // B tile: 32 rows (k=c') x 16 chunks (n=p)
            int r = i >> 4, c = i & 15;
            CPA16(base + OU_BH + r * OB_STRIDE + c * 16, (const char*)(Bh + (long)(kk + r) * HWN + c * 8));
        }
    };

    stage(0, 0);
    CPA_COMMIT();
    const int S = 8;  // K=256 / 32
    for (int s = 0; s < S; s++) {
        if (s + 1 < S) { stage((s + 1) & 1, (s + 1) * 32); CPA_COMMIT(); CPA_WAIT1(); }
        else CPA_WAIT0();
        __syncthreads();
        uint32_t base = sb + (s & 1) * OU_BUF;
#pragma unroll
        for (int ks = 0; ks < 32; ks += 16) {
            uint32_t afh[4][4], bfh[4][2];
#pragma unroll
            for (int i = 0; i < 4; i++) {
                uint32_t ao = (wm + i * 16 + (lane & 15)) * 80 + ks * 2 + (lane >> 4) * 16;
                ldsm4(afh[i], base + OU_AH + ao);
            }
#pragma unroll
            for (int j = 0; j < 2; j++) {
                uint32_t bo = (ks + (lane & 15)) * OB_STRIDE + (wn + j * 16 + (lane >> 4) * 8) * 2;
                uint32_t r[4];
                ldsm4t(r, base + OU_BH + bo);
                bfh[2 * j][0] = r[0]; bfh[2 * j][1] = r[1];
                bfh[2 * j + 1][0] = r[2]; bfh[2 * j + 1][1] = r[3];
            }
#pragma unroll
            for (int i = 0; i < 4; i++)
#pragma unroll
                for (int j = 0; j < 4; j++)
                    mma_f16(acc[i][j], afh[i], bfh[j]);
        }
        __syncthreads();
    }

#pragma unroll
    for (int i = 0; i < 4; i++) {
        int m = mt * 128 + wm + i * 16 + (lane >> 2);
        float d0 = g_d[b][m], d1 = g_d[b][m + 8];
        float* O0 = out + ((long)(b * CCH + m)) * HWN + pt * 128;
        float* O1 = O0 + 8L * HWN;
#pragma unroll
        for (int j = 0; j < 4; j++) {
            int n = wn + j * 8 + (lane & 3) * 2;
            *(float2*)(O0 + n) = make_float2(acc[i][j][0] + d0, acc[i][j][1] + d0);
            *(float2*)(O1 + n) = make_float2(acc[i][j][2] + d1, acc[i][j][3] + d1);
        }
    }
}

// ================= launch =================
extern "C" void kernel_launch(void* const* d_in, const int* in_sizes, int n_in,
                              void* d_out, int out_size) {
    const float* x = (const float*)d_in[0];

    static bool attr_done = false;
    if (!attr_done) {
        cudaFuncSetAttribute(gram_mma_kernel, cudaFuncAttributeMaxDynamicSharedMemorySize, GR_SMEM);
        cudaFuncSetAttribute(out_mma_kernel,  cudaFuncAttributeMaxDynamicSharedMemorySize, OU_SMEM);
        attr_done = true;
    }

    prep_kernel<<<dim3(CCH, BATCH), 256>>>(x);
    gram_mma_kernel<<<dim3(4, 4, BATCH), 256, GR_SMEM>>>();
    reduceG_cov_kernel<<<dim3(8, 8), 256>>>();
    proj_kernel<<<96, 256>>>(
        (const float*)d_in[1], (const float*)d_in[2], (const float*)d_in[3], (const float*)d_in[4],
        (const float*)d_in[5], (const float*)d_in[6], (const float*)d_in[7], (const float*)d_in[8],
        (const float*)d_in[9], (const float*)d_in[10], (const float*)d_in[11], (const float*)d_in[12]);
    t1_kernel<<<dim3(4, 4, BATCH), 256>>>();
    m_kernel<<<dim3(4, 4, BATCH), 256>>>();
    p_kernel<<<dim3(4, 4, BATCH), 256>>>();
    out_mma_kernel<<<dim3(32, 2, BATCH), 256, OU_SMEM>>>((float*)d_out);
}